// round 1
// baseline (speedup 1.0000x reference)
#include <cuda_runtime.h>
#include <math.h>

// Problem constants
#define Bsz  2
#define Tseq 2048
#define Cdim 2048
#define Hh   16
#define Dh   128
#define Mrows (Bsz*Tseq)   // 4096

// -------- scratch (device globals; no allocation allowed) --------
__device__ float g_q[(size_t)Mrows * Cdim];
__device__ float g_k[(size_t)Mrows * Cdim];
__device__ float g_v[(size_t)Mrows * Cdim];
__device__ float g_o[(size_t)Mrows * Cdim];

// ============================================================================
// SGEMM with bias: C[M,N] = A[M,K] @ B[K,N] + bias[N]
// 128x128 block tile, BK=16, 256 threads, 8x8 per-thread register tile.
// ============================================================================
#define GBM 128
#define GBN 128
#define GBK 16

__global__ __launch_bounds__(256) void sgemm_bias_kernel(
    const float* __restrict__ A, const float* __restrict__ Bm,
    const float* __restrict__ bias, float* __restrict__ Cm,
    int Md, int Nd, int Kd)
{
    __shared__ float As[GBK][GBM + 4];   // stored transposed: As[k][m]
    __shared__ float Bs[GBK][GBN + 4];

    const int tid = threadIdx.x;
    const int tx = tid & 15;     // 0..15 -> output cols
    const int ty = tid >> 4;     // 0..15 -> output rows
    const int m0 = blockIdx.y * GBM;
    const int n0 = blockIdx.x * GBN;

    float acc[8][8];
#pragma unroll
    for (int i = 0; i < 8; ++i)
#pragma unroll
        for (int j = 0; j < 8; ++j) acc[i][j] = 0.f;

    for (int k0 = 0; k0 < Kd; k0 += GBK) {
        // Load A tile (128x16), store transposed into As.
#pragma unroll
        for (int l = 0; l < 2; ++l) {
            int lin = tid + l * 256;          // 0..511
            int r   = lin >> 2;               // 0..127
            int c4  = (lin & 3) * 4;          // 0,4,8,12
            float4 v = *(const float4*)(A + (size_t)(m0 + r) * Kd + k0 + c4);
            As[c4 + 0][r] = v.x;
            As[c4 + 1][r] = v.y;
            As[c4 + 2][r] = v.z;
            As[c4 + 3][r] = v.w;
        }
        // Load B tile (16x128).
#pragma unroll
        for (int l = 0; l < 2; ++l) {
            int lin = tid + l * 256;          // 0..511
            int r   = lin >> 5;               // 0..15
            int c4  = (lin & 31) * 4;         // 0..124
            *(float4*)(&Bs[r][c4]) =
                *(const float4*)(Bm + (size_t)(k0 + r) * Nd + n0 + c4);
        }
        __syncthreads();

#pragma unroll
        for (int k = 0; k < GBK; ++k) {
            float a[8], b[8];
            *(float4*)(a)     = *(const float4*)(&As[k][ty * 8]);
            *(float4*)(a + 4) = *(const float4*)(&As[k][ty * 8 + 4]);
            *(float4*)(b)     = *(const float4*)(&Bs[k][tx * 8]);
            *(float4*)(b + 4) = *(const float4*)(&Bs[k][tx * 8 + 4]);
#pragma unroll
            for (int i = 0; i < 8; ++i)
#pragma unroll
                for (int j = 0; j < 8; ++j)
                    acc[i][j] = fmaf(a[i], b[j], acc[i][j]);
        }
        __syncthreads();
    }

    const int row0 = m0 + ty * 8;
    const int col0 = n0 + tx * 8;
    float bb[8];
#pragma unroll
    for (int j = 0; j < 8; ++j) bb[j] = bias[col0 + j];
#pragma unroll
    for (int i = 0; i < 8; ++i) {
        float4 v0 = make_float4(acc[i][0] + bb[0], acc[i][1] + bb[1],
                                acc[i][2] + bb[2], acc[i][3] + bb[3]);
        float4 v1 = make_float4(acc[i][4] + bb[4], acc[i][5] + bb[5],
                                acc[i][6] + bb[6], acc[i][7] + bb[7]);
        *(float4*)(Cm + (size_t)(row0 + i) * Nd + col0)     = v0;
        *(float4*)(Cm + (size_t)(row0 + i) * Nd + col0 + 4) = v1;
    }
}

// ============================================================================
// Flash attention with ALiBi + causal mask.
// One block = 64 queries of one (b,h). Key tiles of 32. fp32 throughout.
// ============================================================================
#define BQ  64
#define BKT 32
#define DST 132            // padded row stride for Q/K/V tiles (floats)
#define SST 33             // padded row stride for score tile

// smem floats: Q 64*132 + K 32*132 + V 32*132 + S 64*33 + 3*64
#define ATTN_SMEM_FLOATS (BQ*DST + BKT*DST + BKT*DST + BQ*SST + 3*BQ)
#define ATTN_SMEM_BYTES  (ATTN_SMEM_FLOATS * 4)

__global__ __launch_bounds__(256) void attn_kernel(
    const float* __restrict__ q, const float* __restrict__ k,
    const float* __restrict__ v, float* __restrict__ o)
{
    extern __shared__ float sm[];
    float* Qs   = sm;                       // [64][132]
    float* Ks   = Qs + BQ * DST;            // [32][132]
    float* Vs   = Ks + BKT * DST;           // [32][132]
    float* Ss   = Vs + BKT * DST;           // [64][33]
    float* rowm = Ss + BQ * SST;            // [64]
    float* rowl = rowm + BQ;                // [64]
    float* rowc = rowl + BQ;                // [64]

    const int tid = threadIdx.x;
    const int i = tid >> 4;                 // 0..15
    const int j = tid & 15;                 // 0..15

    const int qbase = blockIdx.x * BQ;
    const int h = blockIdx.y;
    const int b = blockIdx.z;

    const float scale = 0.08838834764831845f;         // 1/sqrt(128)
    const float slope = exp2f(-0.5f * (float)(h + 1)); // ALiBi slope for H=16

    const size_t headoff = (size_t)b * Tseq * Cdim + (size_t)h * Dh;

    // Load Q tile (64 x 128)
#pragma unroll
    for (int l = 0; l < 8; ++l) {
        int lin = tid + l * 256;            // 0..2047
        int r   = lin >> 5;                 // 0..63
        int c4  = (lin & 31) * 4;           // 0..124
        *(float4*)(Qs + r * DST + c4) =
            *(const float4*)(q + headoff + (size_t)(qbase + r) * Cdim + c4);
    }
    if (tid < BQ) { rowm[tid] = -INFINITY; rowl[tid] = 0.f; }

    float acc[4][8];
#pragma unroll
    for (int rr = 0; rr < 4; ++rr)
#pragma unroll
        for (int cc = 0; cc < 8; ++cc) acc[rr][cc] = 0.f;

    const int ntiles = (qbase >> 5) + 2;    // causal: keys 0 .. qbase+63

    for (int kt = 0; kt < ntiles; ++kt) {
        const int kbase = kt * BKT;
        __syncthreads();   // protect Ks/Vs/Ss from previous iteration readers

        // Load K,V tiles (32 x 128 each)
#pragma unroll
        for (int l = 0; l < 4; ++l) {
            int lin = tid + l * 256;        // 0..1023
            int r   = lin >> 5;             // 0..31
            int c4  = (lin & 31) * 4;
            size_t goff = headoff + (size_t)(kbase + r) * Cdim + c4;
            *(float4*)(Ks + r * DST + c4) = *(const float4*)(k + goff);
            *(float4*)(Vs + r * DST + c4) = *(const float4*)(v + goff);
        }
        __syncthreads();

        // Scores: rows i+16*rr (4), cols j+16*cc (2)
        float s[4][2];
#pragma unroll
        for (int rr = 0; rr < 4; ++rr) { s[rr][0] = 0.f; s[rr][1] = 0.f; }

        const float* krow0 = Ks + j * DST;
        const float* krow1 = Ks + (j + 16) * DST;
#pragma unroll 4
        for (int d4 = 0; d4 < Dh; d4 += 4) {
            float4 k0 = *(const float4*)(krow0 + d4);
            float4 k1 = *(const float4*)(krow1 + d4);
#pragma unroll
            for (int rr = 0; rr < 4; ++rr) {
                float4 qv = *(const float4*)(Qs + (i + 16 * rr) * DST + d4);
                s[rr][0] += qv.x * k0.x + qv.y * k0.y + qv.z * k0.z + qv.w * k0.w;
                s[rr][1] += qv.x * k1.x + qv.y * k1.y + qv.z * k1.z + qv.w * k1.w;
            }
        }
#pragma unroll
        for (int rr = 0; rr < 4; ++rr) {
            int qg = qbase + i + 16 * rr;
#pragma unroll
            for (int cc = 0; cc < 2; ++cc) {
                int kg = kbase + j + 16 * cc;
                float val = s[rr][cc] * scale + slope * (float)(kg - (Tseq - 1));
                if (kg > qg) val = -1e30f;
                Ss[(i + 16 * rr) * SST + j + 16 * cc] = val;
            }
        }
        __syncthreads();

        // Online softmax: one thread per query row
        if (tid < BQ) {
            float* srow = Ss + tid * SST;
            float tm = -1e30f;
#pragma unroll
            for (int c = 0; c < BKT; ++c) tm = fmaxf(tm, srow[c]);
            float mold = rowm[tid];
            float mnew = fmaxf(mold, tm);
            float corr = __expf(mold - mnew);     // 0 on first tile (mold=-inf)
            float ssum = 0.f;
#pragma unroll
            for (int c = 0; c < BKT; ++c) {
                float p = __expf(srow[c] - mnew);
                srow[c] = p;
                ssum += p;
            }
            rowl[tid] = rowl[tid] * corr + ssum;
            rowm[tid] = mnew;
            rowc[tid] = corr;
        }
        __syncthreads();

        // Rescale accumulators and add P @ V
#pragma unroll
        for (int rr = 0; rr < 4; ++rr) {
            float cf = rowc[i + 16 * rr];
#pragma unroll
            for (int cc = 0; cc < 8; ++cc) acc[rr][cc] *= cf;
        }
#pragma unroll 4
        for (int kk = 0; kk < BKT; ++kk) {
            float vv[8];
#pragma unroll
            for (int cc = 0; cc < 8; ++cc) vv[cc] = Vs[kk * DST + j + 16 * cc];
#pragma unroll
            for (int rr = 0; rr < 4; ++rr) {
                float p = Ss[(i + 16 * rr) * SST + kk];
#pragma unroll
                for (int cc = 0; cc < 8; ++cc)
                    acc[rr][cc] = fmaf(p, vv[cc], acc[rr][cc]);
            }
        }
    }
    __syncthreads();

    // Stage normalized output through Qs for coalesced global stores.
#pragma unroll
    for (int rr = 0; rr < 4; ++rr) {
        float inv = 1.f / rowl[i + 16 * rr];
#pragma unroll
        for (int cc = 0; cc < 8; ++cc)
            Qs[(i + 16 * rr) * DST + j + 16 * cc] = acc[rr][cc] * inv;
    }
    __syncthreads();
#pragma unroll
    for (int l = 0; l < 8; ++l) {
        int lin = tid + l * 256;
        int r   = lin >> 5;
        int c4  = (lin & 31) * 4;
        *(float4*)(o + headoff + (size_t)(qbase + r) * Cdim + c4) =
            *(const float4*)(Qs + r * DST + c4);
    }
}

// ============================================================================
// Launch
// ============================================================================
extern "C" void kernel_launch(void* const* d_in, const int* in_sizes, int n_in,
                              void* d_out, int out_size)
{
    const float* x  = (const float*)d_in[0];
    const float* Wq = (const float*)d_in[1];
    const float* bq = (const float*)d_in[2];
    const float* Wk = (const float*)d_in[3];
    const float* bk = (const float*)d_in[4];
    const float* Wv = (const float*)d_in[5];
    const float* bv = (const float*)d_in[6];
    const float* Wo = (const float*)d_in[7];
    const float* bo = (const float*)d_in[8];
    float* out = (float*)d_out;

    float *qp, *kp, *vp, *op;
    cudaGetSymbolAddress((void**)&qp, g_q);
    cudaGetSymbolAddress((void**)&kp, g_k);
    cudaGetSymbolAddress((void**)&vp, g_v);
    cudaGetSymbolAddress((void**)&op, g_o);

    dim3 gg(Cdim / GBN, Mrows / GBM);   // (16, 32)
    sgemm_bias_kernel<<<gg, 256>>>(x, Wq, bq, qp, Mrows, Cdim, Cdim);
    sgemm_bias_kernel<<<gg, 256>>>(x, Wk, bk, kp, Mrows, Cdim, Cdim);
    sgemm_bias_kernel<<<gg, 256>>>(x, Wv, bv, vp, Mrows, Cdim, Cdim);

    cudaFuncSetAttribute(attn_kernel,
                         cudaFuncAttributeMaxDynamicSharedMemorySize,
                         ATTN_SMEM_BYTES);
    dim3 ga(Tseq / BQ, Hh, Bsz);        // (32, 16, 2)
    attn_kernel<<<ga, 256, ATTN_SMEM_BYTES>>>(qp, kp, vp, op);

    sgemm_bias_kernel<<<gg, 256>>>(op, Wo, bo, out, Mrows, Cdim, Cdim);
}

// round 3
// speedup vs baseline: 1.7852x; 1.7852x over previous
#include <cuda_runtime.h>
#include <math.h>
#include <stdint.h>

// Problem constants
#define Bsz  2
#define Tseq 2048
#define Cdim 2048
#define Hh   16
#define Dh   128
#define Mrows (Bsz*Tseq)   // 4096

// -------- scratch (device globals; no allocation allowed) --------
__device__ float g_q[(size_t)Mrows * Cdim];
__device__ float g_k[(size_t)Mrows * Cdim];
__device__ float g_v[(size_t)Mrows * Cdim];
__device__ float g_o[(size_t)Mrows * Cdim];
__device__ float g_xr[(size_t)Mrows * Cdim];     // tf32-rounded x
__device__ float g_wt[4][(size_t)Cdim * Cdim];   // transposed + rounded weights

// ============================================================================
// Helpers
// ============================================================================
__device__ __forceinline__ float tf32r(float x) {
    uint32_t r;
    asm("cvt.rna.tf32.f32 %0, %1;" : "=r"(r) : "f"(x));
    return __uint_as_float(r);
}

__device__ __forceinline__ uint32_t smem_u32(const void* p) {
    uint32_t a;
    asm("{ .reg .u64 t; cvta.to.shared.u64 t, %1; cvt.u32.u64 %0, t; }"
        : "=r"(a) : "l"(p));
    return a;
}

#define CP16(sa, ga) \
    asm volatile("cp.async.cg.shared.global [%0], [%1], 16;" \
                 :: "r"(sa), "l"(ga) : "memory")

#define MMA_TF32(c, a, b) \
    asm volatile("mma.sync.aligned.m16n8k8.row.col.f32.tf32.tf32.f32 " \
        "{%0,%1,%2,%3},{%4,%5,%6,%7},{%8,%9},{%0,%1,%2,%3};" \
        : "+f"((c)[0]), "+f"((c)[1]), "+f"((c)[2]), "+f"((c)[3]) \
        : "r"((a)[0]), "r"((a)[1]), "r"((a)[2]), "r"((a)[3]), \
          "r"((b)[0]), "r"((b)[1]))

// ============================================================================
// round x to tf32
// ============================================================================
__global__ __launch_bounds__(256) void round_tf32_k(
    const float* __restrict__ in, float* __restrict__ out)
{
    size_t i = ((size_t)blockIdx.x * 256 + threadIdx.x) * 4;
    float4 v = *(const float4*)(in + i);
    v.x = tf32r(v.x); v.y = tf32r(v.y); v.z = tf32r(v.z); v.w = tf32r(v.w);
    *(float4*)(out + i) = v;
}

// ============================================================================
// Transpose 2048x2048 f32 with tf32 rounding
// ============================================================================
__global__ __launch_bounds__(256) void transpose_k(
    const float* __restrict__ in, float* __restrict__ out)
{
    __shared__ float t[32][33];
    const int tx = threadIdx.x, ty = threadIdx.y;
    const int x = blockIdx.x * 32 + tx;
    const int y0 = blockIdx.y * 32;
#pragma unroll
    for (int i = 0; i < 32; i += 8)
        t[ty + i][tx] = in[(size_t)(y0 + ty + i) * Cdim + x];
    __syncthreads();
    const int xo = blockIdx.y * 32 + tx;
    const int yo0 = blockIdx.x * 32;
#pragma unroll
    for (int i = 0; i < 32; i += 8)
        out[(size_t)(yo0 + ty + i) * Cdim + xo] = tf32r(t[tx][ty + i]);
}

// ============================================================================
// tf32 mma.sync GEMM: C[M,2048] = A[M,2048] @ Bt[2048,2048]^T + bias
// CTA 128x128, BK=32, 3-stage cp.async, 4 warps (2x2), warp tile 64x64.
//
// Swizzled smem layout (per 128x32 tile, float index):
//   addr(r,k) = (k>>3)*1024 + r*8 + ((k&7) ^ (((r>>2)&1)*4))
// -> every fragment LDS is 32-bank conflict-free; cp.async dests stay 16B
//    contiguous (the XOR flips whole 4-float groups).
// ============================================================================
#define GBM 128
#define GBN 128
#define GBK 32
#define NST 3
#define TILE_FLOATS (GBM * GBK)            // 4096
#define STAGE_FLOATS (2 * TILE_FLOATS)     // 8192
#define STAGE_BYTES  (STAGE_FLOATS * 4)    // 32768
#define GEMM_SMEM (NST * STAGE_BYTES)      // 98304

__global__ __launch_bounds__(128, 1) void gemm_mma_kernel(
    const float* __restrict__ A, const float* __restrict__ Bt,
    const float* __restrict__ bias, float* __restrict__ Cm)
{
    extern __shared__ float sm[];
    const uint32_t smbase = smem_u32(sm);
    const int tid  = threadIdx.x;
    const int lane = tid & 31;
    const int wid  = tid >> 5;
    const int wm   = wid >> 1;       // 0..1
    const int wn   = wid & 1;        // 0..1
    const int m0   = blockIdx.y * GBM;
    const int n0   = blockIdx.x * GBN;
    const int g    = lane >> 2;      // 0..7
    const int t    = lane & 3;       // 0..3

    // Per-thread row offsets into a tile (float index, k-block 0)
    int rowA[8], rowB[8];
#pragma unroll
    for (int mi = 0; mi < 4; ++mi) {
        int r0 = wm * 64 + mi * 16 + g;
        int sw = ((r0 >> 2) & 1) << 2;      // same for r0 and r0+8
        rowA[2 * mi]     = r0 * 8 + (t ^ sw);
        rowA[2 * mi + 1] = rowA[2 * mi] + 64;
    }
#pragma unroll
    for (int ni = 0; ni < 8; ++ni) {
        int nr = wn * 64 + ni * 8 + g;
        int sw = ((nr >> 2) & 1) << 2;
        rowB[ni] = nr * 8 + (t ^ sw);
    }

    float acc[4][8][4];
#pragma unroll
    for (int mi = 0; mi < 4; ++mi)
#pragma unroll
        for (int ni = 0; ni < 8; ++ni)
#pragma unroll
            for (int x = 0; x < 4; ++x) acc[mi][ni][x] = 0.f;

    // cp.async tile loader: 8 chunks of 16B per tile per thread
    const int lr  = tid >> 3;              // base row for this thread's chunks? no:
    // chunk assignment: lin = i*128+tid; r=lin>>3 (0..127), c4=(lin&7)*4
    auto load_stage = [&](int s, int k0) {
        uint32_t ab = smbase + (uint32_t)s * STAGE_BYTES;
        uint32_t bb = ab + TILE_FLOATS * 4;
        const float* Ap = A  + (size_t)m0 * Cdim + k0;
        const float* Bp = Bt + (size_t)n0 * Cdim + k0;
#pragma unroll
        for (int i = 0; i < 8; ++i) {
            int lin = i * 128 + tid;
            int r   = lin >> 3;
            int c4  = (lin & 7) * 4;
            int sw  = ((r >> 2) & 1) << 2;
            uint32_t off = 4u * (uint32_t)((c4 >> 3) * 1024 + r * 8 + ((c4 & 7) ^ sw));
            CP16(ab + off, Ap + (size_t)r * Cdim + c4);
            CP16(bb + off, Bp + (size_t)r * Cdim + c4);
        }
    };
    (void)lr;

    // prologue: stages 0,1
    load_stage(0, 0);
    asm volatile("cp.async.commit_group;" ::: "memory");
    load_stage(1, GBK);
    asm volatile("cp.async.commit_group;" ::: "memory");

    const int NIT = Cdim / GBK;            // 64
    for (int it = 0; it < NIT; ++it) {
        asm volatile("cp.async.wait_group 1;" ::: "memory");
        __syncthreads();

        const int nx = it + 2;
        if (nx < NIT) {
            int s = nx % NST;
            load_stage(s, nx * GBK);
        }
        asm volatile("cp.async.commit_group;" ::: "memory");

        const float* As  = sm + (it % NST) * STAGE_FLOATS;
        const float* Bs2 = As + TILE_FLOATS;

#pragma unroll
        for (int ks = 0; ks < 4; ++ks) {
            const float* Ak = As  + ks * 1024;
            const float* Bk = Bs2 + ks * 1024;
            uint32_t a[4][4], b[8][2];
#pragma unroll
            for (int mi = 0; mi < 4; ++mi) {
                a[mi][0] = __float_as_uint(Ak[rowA[2 * mi]]);
                a[mi][1] = __float_as_uint(Ak[rowA[2 * mi + 1]]);
                a[mi][2] = __float_as_uint(Ak[rowA[2 * mi] ^ 4]);
                a[mi][3] = __float_as_uint(Ak[rowA[2 * mi + 1] ^ 4]);
            }
#pragma unroll
            for (int ni = 0; ni < 8; ++ni) {
                b[ni][0] = __float_as_uint(Bk[rowB[ni]]);
                b[ni][1] = __float_as_uint(Bk[rowB[ni] ^ 4]);
            }
#pragma unroll
            for (int mi = 0; mi < 4; ++mi)
#pragma unroll
                for (int ni = 0; ni < 8; ++ni)
                    MMA_TF32(acc[mi][ni], a[mi], b[ni]);
        }
    }

    // epilogue: direct stores with bias
#pragma unroll
    for (int mi = 0; mi < 4; ++mi) {
        int r0 = m0 + wm * 64 + mi * 16 + g;
#pragma unroll
        for (int ni = 0; ni < 8; ++ni) {
            int col = n0 + wn * 64 + ni * 8 + 2 * t;
            float2 bb = *(const float2*)(bias + col);
            float2 v0 = make_float2(acc[mi][ni][0] + bb.x, acc[mi][ni][1] + bb.y);
            float2 v1 = make_float2(acc[mi][ni][2] + bb.x, acc[mi][ni][3] + bb.y);
            *(float2*)(Cm + (size_t)r0 * Cdim + col)       = v0;
            *(float2*)(Cm + (size_t)(r0 + 8) * Cdim + col) = v1;
        }
    }
}

// ============================================================================
// Flash attention with ALiBi + causal mask (fp32; epilogue rounds to tf32).
// ============================================================================
#define BQ  64
#define BKT 32
#define DST 132
#define SST 33
#define ATTN_SMEM_FLOATS (BQ*DST + BKT*DST + BKT*DST + BQ*SST + 3*BQ)
#define ATTN_SMEM_BYTES  (ATTN_SMEM_FLOATS * 4)

__global__ __launch_bounds__(256) void attn_kernel(
    const float* __restrict__ q, const float* __restrict__ k,
    const float* __restrict__ v, float* __restrict__ o)
{
    extern __shared__ float sm[];
    float* Qs   = sm;
    float* Ks   = Qs + BQ * DST;
    float* Vs   = Ks + BKT * DST;
    float* Ss   = Vs + BKT * DST;
    float* rowm = Ss + BQ * SST;
    float* rowl = rowm + BQ;
    float* rowc = rowl + BQ;

    const int tid = threadIdx.x;
    const int i = tid >> 4;
    const int j = tid & 15;

    const int qbase = blockIdx.x * BQ;
    const int h = blockIdx.y;
    const int b = blockIdx.z;

    const float scale = 0.08838834764831845f;
    const float slope = exp2f(-0.5f * (float)(h + 1));

    const size_t headoff = (size_t)b * Tseq * Cdim + (size_t)h * Dh;

#pragma unroll
    for (int l = 0; l < 8; ++l) {
        int lin = tid + l * 256;
        int r   = lin >> 5;
        int c4  = (lin & 31) * 4;
        *(float4*)(Qs + r * DST + c4) =
            *(const float4*)(q + headoff + (size_t)(qbase + r) * Cdim + c4);
    }
    if (tid < BQ) { rowm[tid] = -INFINITY; rowl[tid] = 0.f; }

    float acc[4][8];
#pragma unroll
    for (int rr = 0; rr < 4; ++rr)
#pragma unroll
        for (int cc = 0; cc < 8; ++cc) acc[rr][cc] = 0.f;

    const int ntiles = (qbase >> 5) + 2;

    for (int kt = 0; kt < ntiles; ++kt) {
        const int kbase = kt * BKT;
        __syncthreads();

#pragma unroll
        for (int l = 0; l < 4; ++l) {
            int lin = tid + l * 256;
            int r   = lin >> 5;
            int c4  = (lin & 31) * 4;
            size_t goff = headoff + (size_t)(kbase + r) * Cdim + c4;
            *(float4*)(Ks + r * DST + c4) = *(const float4*)(k + goff);
            *(float4*)(Vs + r * DST + c4) = *(const float4*)(v + goff);
        }
        __syncthreads();

        float s[4][2];
#pragma unroll
        for (int rr = 0; rr < 4; ++rr) { s[rr][0] = 0.f; s[rr][1] = 0.f; }

        const float* krow0 = Ks + j * DST;
        const float* krow1 = Ks + (j + 16) * DST;
#pragma unroll 4
        for (int d4 = 0; d4 < Dh; d4 += 4) {
            float4 k0 = *(const float4*)(krow0 + d4);
            float4 k1 = *(const float4*)(krow1 + d4);
#pragma unroll
            for (int rr = 0; rr < 4; ++rr) {
                float4 qv = *(const float4*)(Qs + (i + 16 * rr) * DST + d4);
                s[rr][0] += qv.x * k0.x + qv.y * k0.y + qv.z * k0.z + qv.w * k0.w;
                s[rr][1] += qv.x * k1.x + qv.y * k1.y + qv.z * k1.z + qv.w * k1.w;
            }
        }
#pragma unroll
        for (int rr = 0; rr < 4; ++rr) {
            int qg = qbase + i + 16 * rr;
#pragma unroll
            for (int cc = 0; cc < 2; ++cc) {
                int kg = kbase + j + 16 * cc;
                float val = s[rr][cc] * scale + slope * (float)(kg - (Tseq - 1));
                if (kg > qg) val = -1e30f;
                Ss[(i + 16 * rr) * SST + j + 16 * cc] = val;
            }
        }
        __syncthreads();

        if (tid < BQ) {
            float* srow = Ss + tid * SST;
            float tm = -1e30f;
#pragma unroll
            for (int c = 0; c < BKT; ++c) tm = fmaxf(tm, srow[c]);
            float mold = rowm[tid];
            float mnew = fmaxf(mold, tm);
            float corr = __expf(mold - mnew);
            float ssum = 0.f;
#pragma unroll
            for (int c = 0; c < BKT; ++c) {
                float p = __expf(srow[c] - mnew);
                srow[c] = p;
                ssum += p;
            }
            rowl[tid] = rowl[tid] * corr + ssum;
            rowm[tid] = mnew;
            rowc[tid] = corr;
        }
        __syncthreads();

#pragma unroll
        for (int rr = 0; rr < 4; ++rr) {
            float cf = rowc[i + 16 * rr];
#pragma unroll
            for (int cc = 0; cc < 8; ++cc) acc[rr][cc] *= cf;
        }
#pragma unroll 4
        for (int kk = 0; kk < BKT; ++kk) {
            float vv[8];
#pragma unroll
            for (int cc = 0; cc < 8; ++cc) vv[cc] = Vs[kk * DST + j + 16 * cc];
#pragma unroll
            for (int rr = 0; rr < 4; ++rr) {
                float p = Ss[(i + 16 * rr) * SST + kk];
#pragma unroll
                for (int cc = 0; cc < 8; ++cc)
                    acc[rr][cc] = fmaf(p, vv[cc], acc[rr][cc]);
            }
        }
    }
    __syncthreads();

    // Normalize + round to tf32 (it feeds the tf32 output GEMM), stage, store.
#pragma unroll
    for (int rr = 0; rr < 4; ++rr) {
        float inv = 1.f / rowl[i + 16 * rr];
#pragma unroll
        for (int cc = 0; cc < 8; ++cc)
            Qs[(i + 16 * rr) * DST + j + 16 * cc] = tf32r(acc[rr][cc] * inv);
    }
    __syncthreads();
#pragma unroll
    for (int l = 0; l < 8; ++l) {
        int lin = tid + l * 256;
        int r   = lin >> 5;
        int c4  = (lin & 31) * 4;
        *(float4*)(o + headoff + (size_t)(qbase + r) * Cdim + c4) =
            *(const float4*)(Qs + r * DST + c4);
    }
}

// ============================================================================
// Launch
// ============================================================================
extern "C" void kernel_launch(void* const* d_in, const int* in_sizes, int n_in,
                              void* d_out, int out_size)
{
    const float* x  = (const float*)d_in[0];
    const float* Wq = (const float*)d_in[1];
    const float* bq = (const float*)d_in[2];
    const float* Wk = (const float*)d_in[3];
    const float* bk = (const float*)d_in[4];
    const float* Wv = (const float*)d_in[5];
    const float* bv = (const float*)d_in[6];
    const float* Wo = (const float*)d_in[7];
    const float* bo = (const float*)d_in[8];
    float* out = (float*)d_out;

    float *qp, *kp, *vp, *op, *xr, *wt;
    cudaGetSymbolAddress((void**)&qp, g_q);
    cudaGetSymbolAddress((void**)&kp, g_k);
    cudaGetSymbolAddress((void**)&vp, g_v);
    cudaGetSymbolAddress((void**)&op, g_o);
    cudaGetSymbolAddress((void**)&xr, g_xr);
    cudaGetSymbolAddress((void**)&wt, g_wt);
    float* wtq = wt;
    float* wtk = wt + (size_t)Cdim * Cdim;
    float* wtv = wt + 2 * (size_t)Cdim * Cdim;
    float* wto = wt + 3 * (size_t)Cdim * Cdim;

    cudaFuncSetAttribute(gemm_mma_kernel,
                         cudaFuncAttributeMaxDynamicSharedMemorySize, GEMM_SMEM);
    cudaFuncSetAttribute(attn_kernel,
                         cudaFuncAttributeMaxDynamicSharedMemorySize, ATTN_SMEM_BYTES);

    // Pre-round inputs to tf32
    round_tf32_k<<<(Mrows * Cdim) / 1024, 256>>>(x, xr);
    dim3 tb(32, 8), tg(Cdim / 32, Cdim / 32);
    transpose_k<<<tg, tb>>>(Wq, wtq);
    transpose_k<<<tg, tb>>>(Wk, wtk);
    transpose_k<<<tg, tb>>>(Wv, wtv);
    transpose_k<<<tg, tb>>>(Wo, wto);

    dim3 gg(Cdim / GBN, Mrows / GBM);   // (16, 32)
    gemm_mma_kernel<<<gg, 128, GEMM_SMEM>>>(xr, wtq, bq, qp);
    gemm_mma_kernel<<<gg, 128, GEMM_SMEM>>>(xr, wtk, bk, kp);
    gemm_mma_kernel<<<gg, 128, GEMM_SMEM>>>(xr, wtv, bv, vp);

    dim3 ga(Tseq / BQ, Hh, Bsz);        // (32, 16, 2)
    attn_kernel<<<ga, 256, ATTN_SMEM_BYTES>>>(qp, kp, vp, op);

    gemm_mma_kernel<<<gg, 128, GEMM_SMEM>>>(op, wto, bo, out);
}

// round 5
// speedup vs baseline: 2.7133x; 1.5199x over previous
#include <cuda_runtime.h>
#include <math.h>
#include <stdint.h>

// Problem constants
#define Bsz  2
#define Tseq 2048
#define Cdim 2048
#define Hh   16
#define Dh   128
#define Mrows (Bsz*Tseq)   // 4096

// -------- scratch (device globals; no allocation allowed) --------
__device__ float g_q[(size_t)Mrows * Cdim];
__device__ float g_k[(size_t)Mrows * Cdim];
__device__ float g_v[(size_t)Mrows * Cdim];
__device__ float g_o[(size_t)Mrows * Cdim];
__device__ float g_xr[(size_t)Mrows * Cdim];     // tf32-rounded x
__device__ float g_wt[4][(size_t)Cdim * Cdim];   // transposed + rounded weights

// ============================================================================
// Helpers
// ============================================================================
__device__ __forceinline__ float tf32r(float x) {
    uint32_t r;
    asm("cvt.rna.tf32.f32 %0, %1;" : "=r"(r) : "f"(x));
    return __uint_as_float(r);
}

__device__ __forceinline__ uint32_t smem_u32(const void* p) {
    uint32_t a;
    asm("{ .reg .u64 t; cvta.to.shared.u64 t, %1; cvt.u32.u64 %0, t; }"
        : "=r"(a) : "l"(p));
    return a;
}

#define CP16(sa, ga) \
    asm volatile("cp.async.cg.shared.global [%0], [%1], 16;" \
                 :: "r"(sa), "l"(ga) : "memory")

#define MMA_TF32(c, a, b) \
    asm volatile("mma.sync.aligned.m16n8k8.row.col.f32.tf32.tf32.f32 " \
        "{%0,%1,%2,%3},{%4,%5,%6,%7},{%8,%9},{%0,%1,%2,%3};" \
        : "+f"((c)[0]), "+f"((c)[1]), "+f"((c)[2]), "+f"((c)[3]) \
        : "r"((a)[0]), "r"((a)[1]), "r"((a)[2]), "r"((a)[3]), \
          "r"((b)[0]), "r"((b)[1]))

#define SW(r) ((((r) >> 2) & 1) << 2)

// ============================================================================
// round x to tf32
// ============================================================================
__global__ __launch_bounds__(256) void round_tf32_k(
    const float* __restrict__ in, float* __restrict__ out)
{
    size_t i = ((size_t)blockIdx.x * 256 + threadIdx.x) * 4;
    float4 v = *(const float4*)(in + i);
    v.x = tf32r(v.x); v.y = tf32r(v.y); v.z = tf32r(v.z); v.w = tf32r(v.w);
    *(float4*)(out + i) = v;
}

// ============================================================================
// Transpose 2048x2048 f32 with tf32 rounding
// ============================================================================
__global__ __launch_bounds__(256) void transpose_k(
    const float* __restrict__ in, float* __restrict__ out)
{
    __shared__ float t[32][33];
    const int tx = threadIdx.x, ty = threadIdx.y;
    const int x = blockIdx.x * 32 + tx;
    const int y0 = blockIdx.y * 32;
#pragma unroll
    for (int i = 0; i < 32; i += 8)
        t[ty + i][tx] = in[(size_t)(y0 + ty + i) * Cdim + x];
    __syncthreads();
    const int xo = blockIdx.y * 32 + tx;
    const int yo0 = blockIdx.x * 32;
#pragma unroll
    for (int i = 0; i < 32; i += 8)
        out[(size_t)(yo0 + ty + i) * Cdim + xo] = tf32r(t[tx][ty + i]);
}

// ============================================================================
// tf32 mma.sync GEMM: C[M,2048] = A[M,2048] @ Bt[2048,2048]^T + bias
// CTA 128x128, BK=32, 3-stage cp.async, 4 warps (2x2), warp tile 64x64.
// ============================================================================
#define GBM 128
#define GBN 128
#define GBK 32
#define NST 3
#define TILE_FLOATS (GBM * GBK)            // 4096
#define STAGE_FLOATS (2 * TILE_FLOATS)     // 8192
#define STAGE_BYTES  (STAGE_FLOATS * 4)    // 32768
#define GEMM_SMEM (NST * STAGE_BYTES)      // 98304

__global__ __launch_bounds__(128, 1) void gemm_mma_kernel(
    const float* __restrict__ A, const float* __restrict__ Bt,
    const float* __restrict__ bias, float* __restrict__ Cm, int round_out)
{
    extern __shared__ float sm[];
    const uint32_t smbase = smem_u32(sm);
    const int tid  = threadIdx.x;
    const int lane = tid & 31;
    const int wid  = tid >> 5;
    const int wm   = wid >> 1;
    const int wn   = wid & 1;
    const int m0   = blockIdx.y * GBM;
    const int n0   = blockIdx.x * GBN;
    const int g    = lane >> 2;
    const int t    = lane & 3;

    int rowA[8], rowB[8];
#pragma unroll
    for (int mi = 0; mi < 4; ++mi) {
        int r0 = wm * 64 + mi * 16 + g;
        int sw = SW(r0);
        rowA[2 * mi]     = r0 * 8 + (t ^ sw);
        rowA[2 * mi + 1] = rowA[2 * mi] + 64;
    }
#pragma unroll
    for (int ni = 0; ni < 8; ++ni) {
        int nr = wn * 64 + ni * 8 + g;
        rowB[ni] = nr * 8 + (t ^ SW(nr));
    }

    float acc[4][8][4];
#pragma unroll
    for (int mi = 0; mi < 4; ++mi)
#pragma unroll
        for (int ni = 0; ni < 8; ++ni)
#pragma unroll
            for (int x = 0; x < 4; ++x) acc[mi][ni][x] = 0.f;

    auto load_stage = [&](int s, int k0) {
        uint32_t ab = smbase + (uint32_t)s * STAGE_BYTES;
        uint32_t bb = ab + TILE_FLOATS * 4;
        const float* Ap = A  + (size_t)m0 * Cdim + k0;
        const float* Bp = Bt + (size_t)n0 * Cdim + k0;
#pragma unroll
        for (int i = 0; i < 8; ++i) {
            int lin = i * 128 + tid;
            int r   = lin >> 3;
            int c4  = (lin & 7) * 4;
            int sw  = SW(r);
            uint32_t off = 4u * (uint32_t)((c4 >> 3) * 1024 + r * 8 + ((c4 & 7) ^ sw));
            CP16(ab + off, Ap + (size_t)r * Cdim + c4);
            CP16(bb + off, Bp + (size_t)r * Cdim + c4);
        }
    };

    load_stage(0, 0);
    asm volatile("cp.async.commit_group;" ::: "memory");
    load_stage(1, GBK);
    asm volatile("cp.async.commit_group;" ::: "memory");

    const int NIT = Cdim / GBK;            // 64
    for (int it = 0; it < NIT; ++it) {
        asm volatile("cp.async.wait_group 1;" ::: "memory");
        __syncthreads();

        const int nx = it + 2;
        if (nx < NIT) {
            int s = nx % NST;
            load_stage(s, nx * GBK);
        }
        asm volatile("cp.async.commit_group;" ::: "memory");

        const float* As  = sm + (it % NST) * STAGE_FLOATS;
        const float* Bs2 = As + TILE_FLOATS;

#pragma unroll
        for (int ks = 0; ks < 4; ++ks) {
            const float* Ak = As  + ks * 1024;
            const float* Bk = Bs2 + ks * 1024;
            uint32_t a[4][4], b[8][2];
#pragma unroll
            for (int mi = 0; mi < 4; ++mi) {
                a[mi][0] = __float_as_uint(Ak[rowA[2 * mi]]);
                a[mi][1] = __float_as_uint(Ak[rowA[2 * mi + 1]]);
                a[mi][2] = __float_as_uint(Ak[rowA[2 * mi] ^ 4]);
                a[mi][3] = __float_as_uint(Ak[rowA[2 * mi + 1] ^ 4]);
            }
#pragma unroll
            for (int ni = 0; ni < 8; ++ni) {
                b[ni][0] = __float_as_uint(Bk[rowB[ni]]);
                b[ni][1] = __float_as_uint(Bk[rowB[ni] ^ 4]);
            }
#pragma unroll
            for (int mi = 0; mi < 4; ++mi)
#pragma unroll
                for (int ni = 0; ni < 8; ++ni)
                    MMA_TF32(acc[mi][ni], a[mi], b[ni]);
        }
    }

#pragma unroll
    for (int mi = 0; mi < 4; ++mi) {
        int r0 = m0 + wm * 64 + mi * 16 + g;
#pragma unroll
        for (int ni = 0; ni < 8; ++ni) {
            int col = n0 + wn * 64 + ni * 8 + 2 * t;
            float2 bb = *(const float2*)(bias + col);
            float2 v0 = make_float2(acc[mi][ni][0] + bb.x, acc[mi][ni][1] + bb.y);
            float2 v1 = make_float2(acc[mi][ni][2] + bb.x, acc[mi][ni][3] + bb.y);
            if (round_out) {
                v0.x = tf32r(v0.x); v0.y = tf32r(v0.y);
                v1.x = tf32r(v1.x); v1.y = tf32r(v1.y);
            }
            *(float2*)(Cm + (size_t)r0 * Cdim + col)       = v0;
            *(float2*)(Cm + (size_t)(r0 + 8) * Cdim + col) = v1;
        }
    }
}

// ============================================================================
// Tensor-core flash attention (tf32 mma.sync) with ALiBi + causal mask.
// CTA: 128 queries, 8 warps (16 rows each); key tiles of 64; D=128.
// Smem (floats): Qs[0,16384) | Ks 2x8192 @16384 | Vt 128x68 @32768 | P 8x1024 @41472
// ============================================================================
#define ABQ 128
#define ABK 64
#define QS_OFF  0
#define KS_OFF  16384
#define KS_STRIDE 8192
#define VT_OFF  32768
#define VT_RS   68
#define P_OFF   (VT_OFF + Dh * VT_RS)          // 41472
#define ATTN_FLOATS (P_OFF + 8 * 1024)         // 49664
#define ATTN_SMEM_BYTES (ATTN_FLOATS * 4)      // 198656

__global__ __launch_bounds__(256, 1) void attn_mma_kernel(
    const float* __restrict__ q, const float* __restrict__ k,
    const float* __restrict__ v, float* __restrict__ o)
{
    extern __shared__ float sm[];
    const uint32_t smb = smem_u32(sm);
    const int tid  = threadIdx.x;
    const int lane = tid & 31;
    const int w    = tid >> 5;
    const int g    = lane >> 2;
    const int t    = lane & 3;

    const int qbase = blockIdx.x * ABQ;
    const int h = blockIdx.y;
    const int b = blockIdx.z;
    const float scale = 0.08838834764831845f;           // 1/sqrt(128)
    const float slope = exp2f(-0.5f * (float)(h + 1));  // ALiBi slope, H=16
    const size_t headoff = (size_t)b * Tseq * Cdim + (size_t)h * Dh;

    // ---- Q tile (cp.async, swizzled, 128x128) ----
    {
        const float* qp = q + headoff + (size_t)qbase * Cdim;
#pragma unroll
        for (int l = 0; l < 16; ++l) {
            int lin = l * 256 + tid;
            int r   = lin >> 5;
            int c4  = (lin & 31) * 4;
            uint32_t off = (uint32_t)(((c4 >> 3) << 10) + (r << 3) + ((c4 & 7) ^ SW(r)));
            CP16(smb + 4u * off, qp + (size_t)r * Cdim + c4);
        }
    }
    asm volatile("cp.async.commit_group;" ::: "memory");

    const int ntiles = (qbase >> 6) + 2;

    auto loadK = [&](int s, int kb) {
        const float* kp = k + headoff + (size_t)kb * Cdim;
        uint32_t base = smb + 4u * (uint32_t)(KS_OFF + s * KS_STRIDE);
#pragma unroll
        for (int l = 0; l < 8; ++l) {
            int lin = l * 256 + tid;
            int r   = lin >> 5;
            int c4  = (lin & 31) * 4;
            uint32_t off = (uint32_t)(((c4 >> 3) << 9) + (r << 3) + ((c4 & 7) ^ SW(r)));
            CP16(base + 4u * off, kp + (size_t)r * Cdim + c4);
        }
    };
    loadK(0, 0);
    asm volatile("cp.async.commit_group;" ::: "memory");

    // ---- V prefetch to registers (one tile ahead) ----
    float4 vreg[8];
    auto ldgV = [&](int kb) {
        const float* vp = v + headoff + (size_t)kb * Cdim;
#pragma unroll
        for (int l = 0; l < 8; ++l) {
            int idx = l * 256 + tid;
            int kk  = idx & 63;
            int d4  = (idx >> 6) * 4;
            vreg[l] = *(const float4*)(vp + (size_t)kk * Cdim + d4);
        }
    };
    ldgV(0);

    // fragment offsets
    const int rq  = w * 16 + g;
    const int a0q = (rq << 3) + (t ^ SW(rq));
    int rowB[8];
#pragma unroll
    for (int ni = 0; ni < 8; ++ni) {
        int nr = ni * 8 + g;
        rowB[ni] = (nr << 3) + (t ^ SW(nr));
    }
    const int pa0 = (g << 3) + (t ^ SW(g));
    float* Pw = sm + P_OFF + w * 1024;

    float oacc[16][4];
#pragma unroll
    for (int i = 0; i < 16; ++i)
#pragma unroll
        for (int x = 0; x < 4; ++x) oacc[i][x] = 0.f;

    float mprev0 = -INFINITY, mprev1 = -INFINITY;
    float l0 = 0.f, l1 = 0.f;
    const int row0 = qbase + rq;
    const int row1 = row0 + 8;

    for (int kt = 0; kt < ntiles; ++kt) {
        const int sk = kt & 1;
        const int kbase = kt * ABK;
        float* Ks = sm + KS_OFF + sk * KS_STRIDE;
        float* Vt = sm + VT_OFF;

        asm volatile("cp.async.wait_group 0;" ::: "memory");
        __syncthreads();                       // K_kt ready; prev PV done

        if (kt + 1 < ntiles) loadK(sk ^ 1, kbase + ABK);
        asm volatile("cp.async.commit_group;" ::: "memory");

        // transpose vregs (V_kt) -> Vt  (conflict-free STS)
#pragma unroll
        for (int l = 0; l < 8; ++l) {
            int idx = l * 256 + tid;
            int kk  = idx & 63;
            int d4  = (idx >> 6) * 4;
            Vt[(d4 + 0) * VT_RS + kk] = vreg[l].x;
            Vt[(d4 + 1) * VT_RS + kk] = vreg[l].y;
            Vt[(d4 + 2) * VT_RS + kk] = vreg[l].z;
            Vt[(d4 + 3) * VT_RS + kk] = vreg[l].w;
        }
        __syncthreads();                       // Vt visible to all before PV

        if (kt + 1 < ntiles) ldgV(kbase + ABK);

        // ---- S = Q K^T ----
        float sacc[8][4];
#pragma unroll
        for (int ni = 0; ni < 8; ++ni)
#pragma unroll
            for (int x = 0; x < 4; ++x) sacc[ni][x] = 0.f;

#pragma unroll
        for (int ks = 0; ks < 16; ++ks) {
            const float* Qk = sm + ks * 1024;
            const float* Kk = Ks + ks * 512;
            uint32_t a[4];
            a[0] = __float_as_uint(Qk[a0q]);
            a[1] = __float_as_uint(Qk[a0q + 64]);
            a[2] = __float_as_uint(Qk[a0q ^ 4]);
            a[3] = __float_as_uint(Qk[(a0q ^ 4) + 64]);
#pragma unroll
            for (int ni = 0; ni < 8; ++ni) {
                uint32_t bb[2];
                bb[0] = __float_as_uint(Kk[rowB[ni]]);
                bb[1] = __float_as_uint(Kk[rowB[ni] ^ 4]);
                MMA_TF32(sacc[ni], a, bb);
            }
        }

        // ---- scale + ALiBi + causal mask; online softmax ----
        float mt0 = -INFINITY, mt1 = -INFINITY;
#pragma unroll
        for (int ni = 0; ni < 8; ++ni) {
            int col = kbase + ni * 8 + 2 * t;
            float al0 = slope * (float)(col - (Tseq - 1));
            float al1 = slope * (float)(col + 1 - (Tseq - 1));
            float v0 = sacc[ni][0] * scale + al0;
            float v1 = sacc[ni][1] * scale + al1;
            float v2 = sacc[ni][2] * scale + al0;
            float v3 = sacc[ni][3] * scale + al1;
            if (col     > row0) v0 = -1e30f;
            if (col + 1 > row0) v1 = -1e30f;
            if (col     > row1) v2 = -1e30f;
            if (col + 1 > row1) v3 = -1e30f;
            sacc[ni][0] = v0; sacc[ni][1] = v1; sacc[ni][2] = v2; sacc[ni][3] = v3;
            mt0 = fmaxf(mt0, fmaxf(v0, v1));
            mt1 = fmaxf(mt1, fmaxf(v2, v3));
        }
        mt0 = fmaxf(mt0, __shfl_xor_sync(0xffffffffu, mt0, 1));
        mt0 = fmaxf(mt0, __shfl_xor_sync(0xffffffffu, mt0, 2));
        mt1 = fmaxf(mt1, __shfl_xor_sync(0xffffffffu, mt1, 1));
        mt1 = fmaxf(mt1, __shfl_xor_sync(0xffffffffu, mt1, 2));
        float mnew0 = fmaxf(mprev0, mt0);
        float mnew1 = fmaxf(mprev1, mt1);
        float corr0 = __expf(mprev0 - mnew0);
        float corr1 = __expf(mprev1 - mnew1);
        float sum0 = 0.f, sum1 = 0.f;
#pragma unroll
        for (int ni = 0; ni < 8; ++ni) {
            float p0 = __expf(sacc[ni][0] - mnew0);
            float p1 = __expf(sacc[ni][1] - mnew0);
            float p2 = __expf(sacc[ni][2] - mnew1);
            float p3 = __expf(sacc[ni][3] - mnew1);
            sum0 += p0 + p1; sum1 += p2 + p3;
            int off = ni * 128 + (g << 3) + ((2 * t) ^ SW(g));
            *(float2*)(Pw + off)      = make_float2(tf32r(p0), tf32r(p1));
            *(float2*)(Pw + off + 64) = make_float2(tf32r(p2), tf32r(p3));
        }
        sum0 += __shfl_xor_sync(0xffffffffu, sum0, 1);
        sum0 += __shfl_xor_sync(0xffffffffu, sum0, 2);
        sum1 += __shfl_xor_sync(0xffffffffu, sum1, 1);
        sum1 += __shfl_xor_sync(0xffffffffu, sum1, 2);
        l0 = l0 * corr0 + sum0;
        l1 = l1 * corr1 + sum1;
        mprev0 = mnew0; mprev1 = mnew1;
#pragma unroll
        for (int i = 0; i < 16; ++i) {
            oacc[i][0] *= corr0; oacc[i][1] *= corr0;
            oacc[i][2] *= corr1; oacc[i][3] *= corr1;
        }
        __syncwarp();

        // ---- O += P V ----
#pragma unroll
        for (int ks = 0; ks < 8; ++ks) {
            const float* Pk = Pw + ks * 128;
            uint32_t a[4];
            a[0] = __float_as_uint(Pk[pa0]);
            a[1] = __float_as_uint(Pk[pa0 + 64]);
            a[2] = __float_as_uint(Pk[pa0 ^ 4]);
            a[3] = __float_as_uint(Pk[(pa0 ^ 4) + 64]);
#pragma unroll
            for (int d = 0; d < 16; ++d) {
                const float* Vr = Vt + (d * 8 + g) * VT_RS + ks * 8 + t;
                uint32_t bb[2];
                bb[0] = __float_as_uint(Vr[0]);
                bb[1] = __float_as_uint(Vr[4]);
                MMA_TF32(oacc[d], a, bb);
            }
        }
    }

    // ---- epilogue: normalize, tf32-round (feeds final GEMM), store ----
    float inv0 = 1.f / l0, inv1 = 1.f / l1;
    float* op0 = o + headoff + (size_t)row0 * Cdim;
    float* op1 = o + headoff + (size_t)row1 * Cdim;
#pragma unroll
    for (int d = 0; d < 16; ++d) {
        int col = d * 8 + 2 * t;
        *(float2*)(op0 + col) = make_float2(tf32r(oacc[d][0] * inv0),
                                            tf32r(oacc[d][1] * inv0));
        *(float2*)(op1 + col) = make_float2(tf32r(oacc[d][2] * inv1),
                                            tf32r(oacc[d][3] * inv1));
    }
}

// ============================================================================
// Launch
// ============================================================================
extern "C" void kernel_launch(void* const* d_in, const int* in_sizes, int n_in,
                              void* d_out, int out_size)
{
    const float* x  = (const float*)d_in[0];
    const float* Wq = (const float*)d_in[1];
    const float* bq = (const float*)d_in[2];
    const float* Wk = (const float*)d_in[3];
    const float* bk = (const float*)d_in[4];
    const float* Wv = (const float*)d_in[5];
    const float* bv = (const float*)d_in[6];
    const float* Wo = (const float*)d_in[7];
    const float* bo = (const float*)d_in[8];
    float* out = (float*)d_out;

    float *qp, *kp, *vp, *op, *xr, *wt;
    cudaGetSymbolAddress((void**)&qp, g_q);
    cudaGetSymbolAddress((void**)&kp, g_k);
    cudaGetSymbolAddress((void**)&vp, g_v);
    cudaGetSymbolAddress((void**)&op, g_o);
    cudaGetSymbolAddress((void**)&xr, g_xr);
    cudaGetSymbolAddress((void**)&wt, g_wt);
    float* wtq = wt;
    float* wtk = wt + (size_t)Cdim * Cdim;
    float* wtv = wt + 2 * (size_t)Cdim * Cdim;
    float* wto = wt + 3 * (size_t)Cdim * Cdim;

    cudaFuncSetAttribute(gemm_mma_kernel,
                         cudaFuncAttributeMaxDynamicSharedMemorySize, GEMM_SMEM);
    cudaFuncSetAttribute(attn_mma_kernel,
                         cudaFuncAttributeMaxDynamicSharedMemorySize, ATTN_SMEM_BYTES);

    round_tf32_k<<<(Mrows * Cdim) / 1024, 256>>>(x, xr);
    dim3 tb(32, 8), tg(Cdim / 32, Cdim / 32);
    transpose_k<<<tg, tb>>>(Wq, wtq);
    transpose_k<<<tg, tb>>>(Wk, wtk);
    transpose_k<<<tg, tb>>>(Wv, wtv);
    transpose_k<<<tg, tb>>>(Wo, wto);

    dim3 gg(Cdim / GBN, Mrows / GBM);   // (16, 32)
    gemm_mma_kernel<<<gg, 128, GEMM_SMEM>>>(xr, wtq, bq, qp, 1);
    gemm_mma_kernel<<<gg, 128, GEMM_SMEM>>>(xr, wtk, bk, kp, 1);
    gemm_mma_kernel<<<gg, 128, GEMM_SMEM>>>(xr, wtv, bv, vp, 1);

    dim3 ga(Tseq / ABQ, Hh, Bsz);       // (16, 16, 2)
    attn_mma_kernel<<<ga, 256, ATTN_SMEM_BYTES>>>(qp, kp, vp, op);

    gemm_mma_kernel<<<gg, 128, GEMM_SMEM>>>(op, wto, bo, out, 0);
}

// round 6
// speedup vs baseline: 2.7874x; 1.0273x over previous
#include <cuda_runtime.h>
#include <math.h>
#include <stdint.h>

// Problem constants
#define Bsz  2
#define Tseq 2048
#define Cdim 2048
#define Hh   16
#define Dh   128
#define Mrows (Bsz*Tseq)   // 4096

// -------- scratch (device globals; no allocation allowed) --------
__device__ float g_q[(size_t)Mrows * Cdim];
__device__ float g_k[(size_t)Mrows * Cdim];
__device__ float g_v[(size_t)Mrows * Cdim];
__device__ float g_o[(size_t)Mrows * Cdim];
__device__ float g_xr[(size_t)Mrows * Cdim];     // tf32-rounded x
__device__ float g_wt[4][(size_t)Cdim * Cdim];   // transposed + rounded weights

// ============================================================================
// Helpers
// ============================================================================
__device__ __forceinline__ float tf32r(float x) {
    uint32_t r;
    asm("cvt.rna.tf32.f32 %0, %1;" : "=r"(r) : "f"(x));
    return __uint_as_float(r);
}

__device__ __forceinline__ uint32_t smem_u32(const void* p) {
    uint32_t a;
    asm("{ .reg .u64 t; cvta.to.shared.u64 t, %1; cvt.u32.u64 %0, t; }"
        : "=r"(a) : "l"(p));
    return a;
}

#define CP16(sa, ga) \
    asm volatile("cp.async.cg.shared.global [%0], [%1], 16;" \
                 :: "r"(sa), "l"(ga) : "memory")

#define MMA_TF32(c, a, b) \
    asm volatile("mma.sync.aligned.m16n8k8.row.col.f32.tf32.tf32.f32 " \
        "{%0,%1,%2,%3},{%4,%5,%6,%7},{%8,%9},{%0,%1,%2,%3};" \
        : "+f"((c)[0]), "+f"((c)[1]), "+f"((c)[2]), "+f"((c)[3]) \
        : "r"((a)[0]), "r"((a)[1]), "r"((a)[2]), "r"((a)[3]), \
          "r"((b)[0]), "r"((b)[1]))

#define SW(r) ((((r) >> 2) & 1) << 2)

// ============================================================================
// round x to tf32
// ============================================================================
__global__ __launch_bounds__(256) void round_tf32_k(
    const float* __restrict__ in, float* __restrict__ out)
{
    size_t i = ((size_t)blockIdx.x * 256 + threadIdx.x) * 4;
    float4 v = *(const float4*)(in + i);
    v.x = tf32r(v.x); v.y = tf32r(v.y); v.z = tf32r(v.z); v.w = tf32r(v.w);
    *(float4*)(out + i) = v;
}

// ============================================================================
// Transpose 2048x2048 f32 with tf32 rounding
// ============================================================================
__global__ __launch_bounds__(256) void transpose_k(
    const float* __restrict__ in, float* __restrict__ out)
{
    __shared__ float t[32][33];
    const int tx = threadIdx.x, ty = threadIdx.y;
    const int x = blockIdx.x * 32 + tx;
    const int y0 = blockIdx.y * 32;
#pragma unroll
    for (int i = 0; i < 32; i += 8)
        t[ty + i][tx] = in[(size_t)(y0 + ty + i) * Cdim + x];
    __syncthreads();
    const int xo = blockIdx.y * 32 + tx;
    const int yo0 = blockIdx.x * 32;
#pragma unroll
    for (int i = 0; i < 32; i += 8)
        out[(size_t)(yo0 + ty + i) * Cdim + xo] = tf32r(t[tx][ty + i]);
}

// ============================================================================
// tf32 mma.sync GEMM: C[M,2048] = A[M,2048] @ Bt[2048,2048]^T + bias
// CTA 128(M) x 256(N), BK=32, 3-stage cp.async, 8 warps (2x4), warp 64x64.
// Swizzle per k-block of 8: off = (k>>3)*ROWS*8 + r*8 + ((k&7) ^ SW(r)).
// ============================================================================
#define GBM 128
#define GBN 256
#define GBK 32
#define NST 3
#define A_FLOATS (GBM * GBK)               // 4096
#define B_FLOATS (GBN * GBK)               // 8192
#define STAGE_FLOATS (A_FLOATS + B_FLOATS) // 12288
#define STAGE_BYTES  (STAGE_FLOATS * 4)    // 49152
#define GEMM_SMEM (NST * STAGE_BYTES)      // 147456

__device__ __forceinline__ void gemm_body(
    const float* __restrict__ A, const float* __restrict__ Bt,
    const float* __restrict__ bias, float* __restrict__ Cm,
    int round_out, float* sm, uint32_t smbase)
{
    const int tid  = threadIdx.x;
    const int lane = tid & 31;
    const int wid  = tid >> 5;
    const int wm   = wid >> 2;       // 0..1
    const int wn   = wid & 3;        // 0..3
    const int m0   = blockIdx.y * GBM;
    const int n0   = blockIdx.x * GBN;
    const int g    = lane >> 2;
    const int t    = lane & 3;

    int rowA[8], rowB[8];
#pragma unroll
    for (int mi = 0; mi < 4; ++mi) {
        int r0 = wm * 64 + mi * 16 + g;
        rowA[2 * mi]     = r0 * 8 + (t ^ SW(r0));
        rowA[2 * mi + 1] = rowA[2 * mi] + 64;
    }
#pragma unroll
    for (int ni = 0; ni < 8; ++ni) {
        int nr = wn * 64 + ni * 8 + g;
        rowB[ni] = nr * 8 + (t ^ SW(nr));
    }

    float acc[4][8][4];
#pragma unroll
    for (int mi = 0; mi < 4; ++mi)
#pragma unroll
        for (int ni = 0; ni < 8; ++ni)
#pragma unroll
            for (int x = 0; x < 4; ++x) acc[mi][ni][x] = 0.f;

    auto load_stage = [&](int s, int k0) {
        uint32_t ab = smbase + (uint32_t)s * STAGE_BYTES;
        uint32_t bb = ab + A_FLOATS * 4;
        const float* Ap = A  + (size_t)m0 * Cdim + k0;
        const float* Bp = Bt + (size_t)n0 * Cdim + k0;
#pragma unroll
        for (int i = 0; i < 4; ++i) {          // A: 128x32
            int lin = i * 256 + tid;
            int r   = lin >> 3;
            int c4  = (lin & 7) * 4;
            uint32_t off = 4u * (uint32_t)((c4 >> 3) * 1024 + r * 8 + ((c4 & 7) ^ SW(r)));
            CP16(ab + off, Ap + (size_t)r * Cdim + c4);
        }
#pragma unroll
        for (int i = 0; i < 8; ++i) {          // B: 256x32
            int lin = i * 256 + tid;
            int r   = lin >> 3;
            int c4  = (lin & 7) * 4;
            uint32_t off = 4u * (uint32_t)((c4 >> 3) * 2048 + r * 8 + ((c4 & 7) ^ SW(r)));
            CP16(bb + off, Bp + (size_t)r * Cdim + c4);
        }
    };

    load_stage(0, 0);
    asm volatile("cp.async.commit_group;" ::: "memory");
    load_stage(1, GBK);
    asm volatile("cp.async.commit_group;" ::: "memory");

    const int NIT = Cdim / GBK;            // 64
    for (int it = 0; it < NIT; ++it) {
        asm volatile("cp.async.wait_group 1;" ::: "memory");
        __syncthreads();

        const int nx = it + 2;
        if (nx < NIT) {
            load_stage(nx % NST, nx * GBK);
        }
        asm volatile("cp.async.commit_group;" ::: "memory");

        const float* As = sm + (it % NST) * STAGE_FLOATS;
        const float* Bs = As + A_FLOATS;

#pragma unroll
        for (int ks = 0; ks < 4; ++ks) {
            const float* Ak = As + ks * 1024;
            const float* Bk = Bs + ks * 2048;
            uint32_t a[4][4], b[8][2];
#pragma unroll
            for (int mi = 0; mi < 4; ++mi) {
                a[mi][0] = __float_as_uint(Ak[rowA[2 * mi]]);
                a[mi][1] = __float_as_uint(Ak[rowA[2 * mi + 1]]);
                a[mi][2] = __float_as_uint(Ak[rowA[2 * mi] ^ 4]);
                a[mi][3] = __float_as_uint(Ak[rowA[2 * mi + 1] ^ 4]);
            }
#pragma unroll
            for (int ni = 0; ni < 8; ++ni) {
                b[ni][0] = __float_as_uint(Bk[rowB[ni]]);
                b[ni][1] = __float_as_uint(Bk[rowB[ni] ^ 4]);
            }
#pragma unroll
            for (int mi = 0; mi < 4; ++mi)
#pragma unroll
                for (int ni = 0; ni < 8; ++ni)
                    MMA_TF32(acc[mi][ni], a[mi], b[ni]);
        }
    }

#pragma unroll
    for (int mi = 0; mi < 4; ++mi) {
        int r0 = m0 + wm * 64 + mi * 16 + g;
#pragma unroll
        for (int ni = 0; ni < 8; ++ni) {
            int col = n0 + wn * 64 + ni * 8 + 2 * t;
            float2 bb = *(const float2*)(bias + col);
            float2 v0 = make_float2(acc[mi][ni][0] + bb.x, acc[mi][ni][1] + bb.y);
            float2 v1 = make_float2(acc[mi][ni][2] + bb.x, acc[mi][ni][3] + bb.y);
            if (round_out) {
                v0.x = tf32r(v0.x); v0.y = tf32r(v0.y);
                v1.x = tf32r(v1.x); v1.y = tf32r(v1.y);
            }
            *(float2*)(Cm + (size_t)r0 * Cdim + col)       = v0;
            *(float2*)(Cm + (size_t)(r0 + 8) * Cdim + col) = v1;
        }
    }
}

// Merged Q/K/V projection: blockIdx.z selects weight/bias/output.
__global__ __launch_bounds__(256, 1) void gemm_qkv_kernel(
    const float* __restrict__ A, const float* __restrict__ WtBase,
    const float* __restrict__ bq, const float* __restrict__ bk,
    const float* __restrict__ bv,
    float* __restrict__ Cq, float* __restrict__ Ck, float* __restrict__ Cv)
{
    extern __shared__ float sm[];
    const int z = blockIdx.z;
    const float* Bt   = WtBase + (size_t)z * Cdim * Cdim;
    const float* bias = (z == 0) ? bq : (z == 1) ? bk : bv;
    float*       Cm   = (z == 0) ? Cq : (z == 1) ? Ck : Cv;
    gemm_body(A, Bt, bias, Cm, 1, sm, smem_u32(sm));
}

// Output projection (no tf32 rounding of the result).
__global__ __launch_bounds__(256, 1) void gemm_o_kernel(
    const float* __restrict__ A, const float* __restrict__ Bt,
    const float* __restrict__ bias, float* __restrict__ Cm)
{
    extern __shared__ float sm[];
    gemm_body(A, Bt, bias, Cm, 0, sm, smem_u32(sm));
}

// ============================================================================
// Tensor-core flash attention (tf32 mma.sync) with ALiBi + causal mask.
// CTA: 128 queries, 8 warps (16 rows each); key tiles of 64; D=128.
// Smem (floats): Qs[0,16384) | Ks 2x8192 @16384 | Vt 128x68 @32768 | P 8x1024 @41472
// ============================================================================
#define ABQ 128
#define ABK 64
#define KS_OFF  16384
#define KS_STRIDE 8192
#define VT_OFF  32768
#define VT_RS   68
#define P_OFF   (VT_OFF + Dh * VT_RS)          // 41472
#define ATTN_FLOATS (P_OFF + 8 * 1024)         // 49664
#define ATTN_SMEM_BYTES (ATTN_FLOATS * 4)      // 198656

__global__ __launch_bounds__(256, 1) void attn_mma_kernel(
    const float* __restrict__ q, const float* __restrict__ k,
    const float* __restrict__ v, float* __restrict__ o)
{
    extern __shared__ float sm[];
    const uint32_t smb = smem_u32(sm);
    const int tid  = threadIdx.x;
    const int lane = tid & 31;
    const int w    = tid >> 5;
    const int g    = lane >> 2;
    const int t    = lane & 3;

    const int qbase = blockIdx.x * ABQ;
    const int h = blockIdx.y;
    const int b = blockIdx.z;
    const float scale = 0.08838834764831845f;           // 1/sqrt(128)
    const float slope = exp2f(-0.5f * (float)(h + 1));  // ALiBi slope, H=16
    const size_t headoff = (size_t)b * Tseq * Cdim + (size_t)h * Dh;

    // ---- Q tile (cp.async, swizzled, 128x128) ----
    {
        const float* qp = q + headoff + (size_t)qbase * Cdim;
#pragma unroll
        for (int l = 0; l < 16; ++l) {
            int lin = l * 256 + tid;
            int r   = lin >> 5;
            int c4  = (lin & 31) * 4;
            uint32_t off = (uint32_t)(((c4 >> 3) << 10) + (r << 3) + ((c4 & 7) ^ SW(r)));
            CP16(smb + 4u * off, qp + (size_t)r * Cdim + c4);
        }
    }
    asm volatile("cp.async.commit_group;" ::: "memory");

    const int ntiles = (qbase >> 6) + 2;

    auto loadK = [&](int s, int kb) {
        const float* kp = k + headoff + (size_t)kb * Cdim;
        uint32_t base = smb + 4u * (uint32_t)(KS_OFF + s * KS_STRIDE);
#pragma unroll
        for (int l = 0; l < 8; ++l) {
            int lin = l * 256 + tid;
            int r   = lin >> 5;
            int c4  = (lin & 31) * 4;
            uint32_t off = (uint32_t)(((c4 >> 3) << 9) + (r << 3) + ((c4 & 7) ^ SW(r)));
            CP16(base + 4u * off, kp + (size_t)r * Cdim + c4);
        }
    };
    loadK(0, 0);
    asm volatile("cp.async.commit_group;" ::: "memory");

    // ---- V prefetch to registers (one tile ahead) ----
    float4 vreg[8];
    auto ldgV = [&](int kb) {
        const float* vp = v + headoff + (size_t)kb * Cdim;
#pragma unroll
        for (int l = 0; l < 8; ++l) {
            int idx = l * 256 + tid;
            int kk  = idx & 63;
            int d4  = (idx >> 6) * 4;
            vreg[l] = *(const float4*)(vp + (size_t)kk * Cdim + d4);
        }
    };
    ldgV(0);

    const int rq  = w * 16 + g;
    const int a0q = (rq << 3) + (t ^ SW(rq));
    int rowB[8];
#pragma unroll
    for (int ni = 0; ni < 8; ++ni) {
        int nr = ni * 8 + g;
        rowB[ni] = (nr << 3) + (t ^ SW(nr));
    }
    const int pa0 = (g << 3) + (t ^ SW(g));
    float* Pw = sm + P_OFF + w * 1024;

    float oacc[16][4];
#pragma unroll
    for (int i = 0; i < 16; ++i)
#pragma unroll
        for (int x = 0; x < 4; ++x) oacc[i][x] = 0.f;

    float mprev0 = -INFINITY, mprev1 = -INFINITY;
    float l0 = 0.f, l1 = 0.f;
    const int row0 = qbase + rq;
    const int row1 = row0 + 8;

    for (int kt = 0; kt < ntiles; ++kt) {
        const int sk = kt & 1;
        const int kbase = kt * ABK;
        float* Ks = sm + KS_OFF + sk * KS_STRIDE;
        float* Vt = sm + VT_OFF;

        asm volatile("cp.async.wait_group 0;" ::: "memory");
        __syncthreads();                       // K_kt ready; prev PV done

        if (kt + 1 < ntiles) loadK(sk ^ 1, kbase + ABK);
        asm volatile("cp.async.commit_group;" ::: "memory");

        // transpose vregs (V_kt) -> Vt  (conflict-free STS)
#pragma unroll
        for (int l = 0; l < 8; ++l) {
            int idx = l * 256 + tid;
            int kk  = idx & 63;
            int d4  = (idx >> 6) * 4;
            Vt[(d4 + 0) * VT_RS + kk] = vreg[l].x;
            Vt[(d4 + 1) * VT_RS + kk] = vreg[l].y;
            Vt[(d4 + 2) * VT_RS + kk] = vreg[l].z;
            Vt[(d4 + 3) * VT_RS + kk] = vreg[l].w;
        }
        __syncthreads();                       // Vt visible before PV

        if (kt + 1 < ntiles) ldgV(kbase + ABK);

        // ---- S = Q K^T ----
        float sacc[8][4];
#pragma unroll
        for (int ni = 0; ni < 8; ++ni)
#pragma unroll
            for (int x = 0; x < 4; ++x) sacc[ni][x] = 0.f;

#pragma unroll
        for (int ks = 0; ks < 16; ++ks) {
            const float* Qk = sm + ks * 1024;
            const float* Kk = Ks + ks * 512;
            uint32_t a[4];
            a[0] = __float_as_uint(Qk[a0q]);
            a[1] = __float_as_uint(Qk[a0q + 64]);
            a[2] = __float_as_uint(Qk[a0q ^ 4]);
            a[3] = __float_as_uint(Qk[(a0q ^ 4) + 64]);
#pragma unroll
            for (int ni = 0; ni < 8; ++ni) {
                uint32_t bb[2];
                bb[0] = __float_as_uint(Kk[rowB[ni]]);
                bb[1] = __float_as_uint(Kk[rowB[ni] ^ 4]);
                MMA_TF32(sacc[ni], a, bb);
            }
        }

        // ---- scale + ALiBi + causal mask; online softmax ----
        float mt0 = -INFINITY, mt1 = -INFINITY;
#pragma unroll
        for (int ni = 0; ni < 8; ++ni) {
            int col = kbase + ni * 8 + 2 * t;
            float al0 = slope * (float)(col - (Tseq - 1));
            float al1 = slope * (float)(col + 1 - (Tseq - 1));
            float v0 = sacc[ni][0] * scale + al0;
            float v1 = sacc[ni][1] * scale + al1;
            float v2 = sacc[ni][2] * scale + al0;
            float v3 = sacc[ni][3] * scale + al1;
            if (col     > row0) v0 = -1e30f;
            if (col + 1 > row0) v1 = -1e30f;
            if (col     > row1) v2 = -1e30f;
            if (col + 1 > row1) v3 = -1e30f;
            sacc[ni][0] = v0; sacc[ni][1] = v1; sacc[ni][2] = v2; sacc[ni][3] = v3;
            mt0 = fmaxf(mt0, fmaxf(v0, v1));
            mt1 = fmaxf(mt1, fmaxf(v2, v3));
        }
        mt0 = fmaxf(mt0, __shfl_xor_sync(0xffffffffu, mt0, 1));
        mt0 = fmaxf(mt0, __shfl_xor_sync(0xffffffffu, mt0, 2));
        mt1 = fmaxf(mt1, __shfl_xor_sync(0xffffffffu, mt1, 1));
        mt1 = fmaxf(mt1, __shfl_xor_sync(0xffffffffu, mt1, 2));
        float mnew0 = fmaxf(mprev0, mt0);
        float mnew1 = fmaxf(mprev1, mt1);
        float corr0 = __expf(mprev0 - mnew0);
        float corr1 = __expf(mprev1 - mnew1);
        float sum0 = 0.f, sum1 = 0.f;
#pragma unroll
        for (int ni = 0; ni < 8; ++ni) {
            float p0 = __expf(sacc[ni][0] - mnew0);
            float p1 = __expf(sacc[ni][1] - mnew0);
            float p2 = __expf(sacc[ni][2] - mnew1);
            float p3 = __expf(sacc[ni][3] - mnew1);
            sum0 += p0 + p1; sum1 += p2 + p3;
            int off = ni * 128 + (g << 3) + ((2 * t) ^ SW(g));
            *(float2*)(Pw + off)      = make_float2(tf32r(p0), tf32r(p1));
            *(float2*)(Pw + off + 64) = make_float2(tf32r(p2), tf32r(p3));
        }
        sum0 += __shfl_xor_sync(0xffffffffu, sum0, 1);
        sum0 += __shfl_xor_sync(0xffffffffu, sum0, 2);
        sum1 += __shfl_xor_sync(0xffffffffu, sum1, 1);
        sum1 += __shfl_xor_sync(0xffffffffu, sum1, 2);
        l0 = l0 * corr0 + sum0;
        l1 = l1 * corr1 + sum1;
        mprev0 = mnew0; mprev1 = mnew1;
#pragma unroll
        for (int i = 0; i < 16; ++i) {
            oacc[i][0] *= corr0; oacc[i][1] *= corr0;
            oacc[i][2] *= corr1; oacc[i][3] *= corr1;
        }
        __syncwarp();

        // ---- O += P V ----
#pragma unroll
        for (int ks = 0; ks < 8; ++ks) {
            const float* Pk = Pw + ks * 128;
            uint32_t a[4];
            a[0] = __float_as_uint(Pk[pa0]);
            a[1] = __float_as_uint(Pk[pa0 + 64]);
            a[2] = __float_as_uint(Pk[pa0 ^ 4]);
            a[3] = __float_as_uint(Pk[(pa0 ^ 4) + 64]);
#pragma unroll
            for (int d = 0; d < 16; ++d) {
                const float* Vr = Vt + (d * 8 + g) * VT_RS + ks * 8 + t;
                uint32_t bb[2];
                bb[0] = __float_as_uint(Vr[0]);
                bb[1] = __float_as_uint(Vr[4]);
                MMA_TF32(oacc[d], a, bb);
            }
        }
    }

    // ---- epilogue: normalize, tf32-round (feeds final GEMM), store ----
    float inv0 = 1.f / l0, inv1 = 1.f / l1;
    float* op0 = o + headoff + (size_t)row0 * Cdim;
    float* op1 = o + headoff + (size_t)row1 * Cdim;
#pragma unroll
    for (int d = 0; d < 16; ++d) {
        int col = d * 8 + 2 * t;
        *(float2*)(op0 + col) = make_float2(tf32r(oacc[d][0] * inv0),
                                            tf32r(oacc[d][1] * inv0));
        *(float2*)(op1 + col) = make_float2(tf32r(oacc[d][2] * inv1),
                                            tf32r(oacc[d][3] * inv1));
    }
}

// ============================================================================
// Launch
// ============================================================================
extern "C" void kernel_launch(void* const* d_in, const int* in_sizes, int n_in,
                              void* d_out, int out_size)
{
    const float* x  = (const float*)d_in[0];
    const float* Wq = (const float*)d_in[1];
    const float* bq = (const float*)d_in[2];
    const float* Wk = (const float*)d_in[3];
    const float* bk = (const float*)d_in[4];
    const float* Wv = (const float*)d_in[5];
    const float* bv = (const float*)d_in[6];
    const float* Wo = (const float*)d_in[7];
    const float* bo = (const float*)d_in[8];
    float* out = (float*)d_out;

    float *qp, *kp, *vp, *op, *xr, *wt;
    cudaGetSymbolAddress((void**)&qp, g_q);
    cudaGetSymbolAddress((void**)&kp, g_k);
    cudaGetSymbolAddress((void**)&vp, g_v);
    cudaGetSymbolAddress((void**)&op, g_o);
    cudaGetSymbolAddress((void**)&xr, g_xr);
    cudaGetSymbolAddress((void**)&wt, g_wt);
    float* wto = wt + 3 * (size_t)Cdim * Cdim;

    cudaFuncSetAttribute(gemm_qkv_kernel,
                         cudaFuncAttributeMaxDynamicSharedMemorySize, GEMM_SMEM);
    cudaFuncSetAttribute(gemm_o_kernel,
                         cudaFuncAttributeMaxDynamicSharedMemorySize, GEMM_SMEM);
    cudaFuncSetAttribute(attn_mma_kernel,
                         cudaFuncAttributeMaxDynamicSharedMemorySize, ATTN_SMEM_BYTES);

    round_tf32_k<<<(Mrows * Cdim) / 1024, 256>>>(x, xr);
    dim3 tb(32, 8), tg(Cdim / 32, Cdim / 32);
    transpose_k<<<tg, tb>>>(Wq, wt);
    transpose_k<<<tg, tb>>>(Wk, wt + (size_t)Cdim * Cdim);
    transpose_k<<<tg, tb>>>(Wv, wt + 2 * (size_t)Cdim * Cdim);
    transpose_k<<<tg, tb>>>(Wo, wto);

    dim3 gq(Cdim / GBN, Mrows / GBM, 3);   // (8, 32, 3)
    gemm_qkv_kernel<<<gq, 256, GEMM_SMEM>>>(xr, wt, bq, bk, bv, qp, kp, vp);

    dim3 ga(Tseq / ABQ, Hh, Bsz);          // (16, 16, 2)
    attn_mma_kernel<<<ga, 256, ATTN_SMEM_BYTES>>>(qp, kp, vp, op);

    dim3 go(Cdim / GBN, Mrows / GBM);      // (8, 32)
    gemm_o_kernel<<<go, 256, GEMM_SMEM>>>(op, wto, bo, out);
}

// round 7
// speedup vs baseline: 5.2816x; 1.8948x over previous
#include <cuda_runtime.h>
#include <cuda_fp16.h>
#include <math.h>
#include <stdint.h>

// Problem constants
#define Bsz  2
#define Tseq 2048
#define Cdim 2048
#define Hh   16
#define Dh   128
#define Mrows (Bsz*Tseq)   // 4096

// -------- scratch (device globals; no allocation allowed) --------
__device__ __half g_q[(size_t)Mrows * Cdim];
__device__ __half g_k[(size_t)Mrows * Cdim];
__device__ __half g_v[(size_t)Mrows * Cdim];
__device__ __half g_o[(size_t)Mrows * Cdim];
__device__ __half g_xh[(size_t)Mrows * Cdim];       // fp16 x
__device__ __half g_wt[4][(size_t)Cdim * Cdim];     // transposed fp16 weights

// ============================================================================
// Helpers
// ============================================================================
__device__ __forceinline__ uint32_t smem_u32(const void* p) {
    uint32_t a;
    asm("{ .reg .u64 t; cvta.to.shared.u64 t, %1; cvt.u32.u64 %0, t; }"
        : "=r"(a) : "l"(p));
    return a;
}

#define CP16(sa, ga) \
    asm volatile("cp.async.cg.shared.global [%0], [%1], 16;" \
                 :: "r"(sa), "l"(ga) : "memory")

#define MMA_F16(c, a, b) \
    asm volatile("mma.sync.aligned.m16n8k16.row.col.f32.f16.f16.f32 " \
        "{%0,%1,%2,%3},{%4,%5,%6,%7},{%8,%9},{%0,%1,%2,%3};" \
        : "+f"((c)[0]), "+f"((c)[1]), "+f"((c)[2]), "+f"((c)[3]) \
        : "r"((a)[0]), "r"((a)[1]), "r"((a)[2]), "r"((a)[3]), \
          "r"((b)[0]), "r"((b)[1]))

#define SW(r) ((((r) >> 2) & 1) << 2)

// ============================================================================
// x -> fp16
// ============================================================================
__global__ __launch_bounds__(256) void round_h_k(
    const float* __restrict__ in, __half* __restrict__ out)
{
    size_t i = ((size_t)blockIdx.x * 256 + threadIdx.x) * 4;
    float4 v = *(const float4*)(in + i);
    __half2 h0 = __floats2half2_rn(v.x, v.y);
    __half2 h1 = __floats2half2_rn(v.z, v.w);
    *(__half2*)(out + i)     = h0;
    *(__half2*)(out + i + 2) = h1;
}

// ============================================================================
// Transpose 2048x2048 f32 -> fp16
// ============================================================================
__global__ __launch_bounds__(256) void transpose_h_k(
    const float* __restrict__ in, __half* __restrict__ out)
{
    __shared__ float t[32][33];
    const int tx = threadIdx.x, ty = threadIdx.y;
    const int x = blockIdx.x * 32 + tx;
    const int y0 = blockIdx.y * 32;
#pragma unroll
    for (int i = 0; i < 32; i += 8)
        t[ty + i][tx] = in[(size_t)(y0 + ty + i) * Cdim + x];
    __syncthreads();
    const int xo = blockIdx.y * 32 + tx;
    const int yo0 = blockIdx.x * 32;
#pragma unroll
    for (int i = 0; i < 32; i += 8)
        out[(size_t)(yo0 + ty + i) * Cdim + xo] = __float2half_rn(t[tx][ty + i]);
}

// ============================================================================
// fp16 mma.sync GEMM: C[M,2048] = A[M,2048] @ Bt[2048,2048]^T + bias
// CTA 128(M) x 256(N), BK=64 halves, 3-stage cp.async, 8 warps, warp 64x64.
// smem viewed as u32 (fp16x2 units); per 64-half row = 32 units:
//   off_u32(r,u) = (u>>3)*ROWS*8 + r*8 + ((u&7) ^ SW(r))
// ============================================================================
#define GBM 128
#define GBN 256
#define GBK 64
#define NST 3
#define A_U32 (GBM * GBK / 2)              // 4096
#define B_U32 (GBN * GBK / 2)              // 8192
#define STAGE_U32 (A_U32 + B_U32)          // 12288
#define STAGE_BYTES (STAGE_U32 * 4)        // 49152
#define GEMM_SMEM (NST * STAGE_BYTES)      // 147456

template<typename OutT>
__device__ __forceinline__ void gemm_body_h(
    const __half* __restrict__ A, const __half* __restrict__ Bt,
    const float* __restrict__ bias, OutT* __restrict__ Cm,
    uint32_t* smu, uint32_t smbase)
{
    const int tid  = threadIdx.x;
    const int lane = tid & 31;
    const int wid  = tid >> 5;
    const int wm   = wid >> 2;       // 0..1
    const int wn   = wid & 3;        // 0..3
    const int m0   = blockIdx.y * GBM;
    const int n0   = blockIdx.x * GBN;
    const int g    = lane >> 2;
    const int t    = lane & 3;

    int rowA[8], rowB[8];
#pragma unroll
    for (int mi = 0; mi < 4; ++mi) {
        int r0 = wm * 64 + mi * 16 + g;
        rowA[2 * mi]     = r0 * 8 + (t ^ SW(r0));
        rowA[2 * mi + 1] = rowA[2 * mi] + 64;
    }
#pragma unroll
    for (int ni = 0; ni < 8; ++ni) {
        int nr = wn * 64 + ni * 8 + g;
        rowB[ni] = nr * 8 + (t ^ SW(nr));
    }

    float acc[4][8][4];
#pragma unroll
    for (int mi = 0; mi < 4; ++mi)
#pragma unroll
        for (int ni = 0; ni < 8; ++ni)
#pragma unroll
            for (int x = 0; x < 4; ++x) acc[mi][ni][x] = 0.f;

    auto load_stage = [&](int s, int k0) {
        uint32_t ab = smbase + (uint32_t)s * STAGE_BYTES;
        uint32_t bb = ab + A_U32 * 4;
        const __half* Ap = A  + (size_t)m0 * Cdim + k0;
        const __half* Bp = Bt + (size_t)n0 * Cdim + k0;
#pragma unroll
        for (int i = 0; i < 4; ++i) {          // A: 128 rows x 8 chunks
            int lin = i * 256 + tid;
            int r   = lin >> 3;
            int cu  = (lin & 7) * 4;           // unit index 0..28
            uint32_t off = 4u * (uint32_t)((cu >> 3) * 1024 + r * 8 + ((cu & 7) ^ SW(r)));
            CP16(ab + off, Ap + (size_t)r * Cdim + cu * 2);
        }
#pragma unroll
        for (int i = 0; i < 8; ++i) {          // B: 256 rows x 8 chunks
            int lin = i * 256 + tid;
            int r   = lin >> 3;
            int cu  = (lin & 7) * 4;
            uint32_t off = 4u * (uint32_t)((cu >> 3) * 2048 + r * 8 + ((cu & 7) ^ SW(r)));
            CP16(bb + off, Bp + (size_t)r * Cdim + cu * 2);
        }
    };

    load_stage(0, 0);
    asm volatile("cp.async.commit_group;" ::: "memory");
    load_stage(1, GBK);
    asm volatile("cp.async.commit_group;" ::: "memory");

    const int NIT = Cdim / GBK;            // 32
    for (int it = 0; it < NIT; ++it) {
        asm volatile("cp.async.wait_group 1;" ::: "memory");
        __syncthreads();

        const int nx = it + 2;
        if (nx < NIT) load_stage(nx % NST, nx * GBK);
        asm volatile("cp.async.commit_group;" ::: "memory");

        const uint32_t* As = smu + (it % NST) * STAGE_U32;
        const uint32_t* Bs = As + A_U32;

#pragma unroll
        for (int ks = 0; ks < 4; ++ks) {      // 4 k16-steps per BK=64
            const uint32_t* Ak = As + ks * 1024;
            const uint32_t* Bk = Bs + ks * 2048;
            uint32_t a[4][4], b[8][2];
#pragma unroll
            for (int mi = 0; mi < 4; ++mi) {
                a[mi][0] = Ak[rowA[2 * mi]];
                a[mi][1] = Ak[rowA[2 * mi + 1]];
                a[mi][2] = Ak[rowA[2 * mi] ^ 4];
                a[mi][3] = Ak[rowA[2 * mi + 1] ^ 4];
            }
#pragma unroll
            for (int ni = 0; ni < 8; ++ni) {
                b[ni][0] = Bk[rowB[ni]];
                b[ni][1] = Bk[rowB[ni] ^ 4];
            }
#pragma unroll
            for (int mi = 0; mi < 4; ++mi)
#pragma unroll
                for (int ni = 0; ni < 8; ++ni)
                    MMA_F16(acc[mi][ni], a[mi], b[ni]);
        }
    }

#pragma unroll
    for (int mi = 0; mi < 4; ++mi) {
        int r0 = m0 + wm * 64 + mi * 16 + g;
#pragma unroll
        for (int ni = 0; ni < 8; ++ni) {
            int col = n0 + wn * 64 + ni * 8 + 2 * t;
            float2 bb = *(const float2*)(bias + col);
            float v0 = acc[mi][ni][0] + bb.x, v1 = acc[mi][ni][1] + bb.y;
            float v2 = acc[mi][ni][2] + bb.x, v3 = acc[mi][ni][3] + bb.y;
            if (sizeof(OutT) == 2) {            // fp16 out
                __half* C = (__half*)Cm;
                *(__half2*)(C + (size_t)r0 * Cdim + col)       = __floats2half2_rn(v0, v1);
                *(__half2*)(C + (size_t)(r0 + 8) * Cdim + col) = __floats2half2_rn(v2, v3);
            } else {                            // fp32 out
                float* C = (float*)Cm;
                *(float2*)(C + (size_t)r0 * Cdim + col)       = make_float2(v0, v1);
                *(float2*)(C + (size_t)(r0 + 8) * Cdim + col) = make_float2(v2, v3);
            }
        }
    }
}

// Merged Q/K/V projection: blockIdx.z selects weight/bias/output.
__global__ __launch_bounds__(256, 1) void gemm_qkv_kernel(
    const __half* __restrict__ A, const __half* __restrict__ WtBase,
    const float* __restrict__ bq, const float* __restrict__ bk,
    const float* __restrict__ bv,
    __half* __restrict__ Cq, __half* __restrict__ Ck, __half* __restrict__ Cv)
{
    extern __shared__ uint32_t smu[];
    const int z = blockIdx.z;
    const __half* Bt  = WtBase + (size_t)z * Cdim * Cdim;
    const float* bias = (z == 0) ? bq : (z == 1) ? bk : bv;
    __half*      Cm   = (z == 0) ? Cq : (z == 1) ? Ck : Cv;
    gemm_body_h<__half>(A, Bt, bias, Cm, smu, smem_u32(smu));
}

// Output projection (fp32 result).
__global__ __launch_bounds__(256, 1) void gemm_o_kernel(
    const __half* __restrict__ A, const __half* __restrict__ Bt,
    const float* __restrict__ bias, float* __restrict__ Cm)
{
    extern __shared__ uint32_t smu[];
    gemm_body_h<float>(A, Bt, bias, Cm, smu, smem_u32(smu));
}

// ============================================================================
// fp16 tensor-core flash attention with ALiBi + causal mask.
// CTA: 128 queries, 8 warps; key tiles of 64; D=128. smem in u32 units:
//   Q [0,8192) | K 2x4096 @8192 | Vt 128x36 @16384 | P 8x512 @20992
// ============================================================================
#define ABQ 128
#define ABK 64
#define KS_OFF   8192
#define KS_STRIDE 4096
#define VT_OFF   16384
#define VT_RSU   36                    // u32 stride per d-row (72 halves)
#define P_OFF    (VT_OFF + Dh * VT_RSU)        // 20992
#define ATTN_U32 (P_OFF + 8 * 512)             // 25088
#define ATTN_SMEM_BYTES (ATTN_U32 * 4)         // 100352

__global__ __launch_bounds__(256, 1) void attn_mma_kernel(
    const __half* __restrict__ q, const __half* __restrict__ k,
    const __half* __restrict__ v, __half* __restrict__ o)
{
    extern __shared__ uint32_t smu[];
    const uint32_t smb = smem_u32(smu);
    const int tid  = threadIdx.x;
    const int lane = tid & 31;
    const int w    = tid >> 5;
    const int g    = lane >> 2;
    const int t    = lane & 3;

    const int qbase = blockIdx.x * ABQ;
    const int h = blockIdx.y;
    const int b = blockIdx.z;
    const float scale = 0.08838834764831845f;           // 1/sqrt(128)
    const float slope = exp2f(-0.5f * (float)(h + 1));  // ALiBi slope, H=16
    const size_t headoff = (size_t)b * Tseq * Cdim + (size_t)h * Dh;

    // ---- Q tile: 128 rows x 256B ----
    {
        const __half* qp = q + headoff + (size_t)qbase * Cdim;
#pragma unroll
        for (int l = 0; l < 8; ++l) {
            int lin = l * 256 + tid;
            int r   = lin >> 4;
            int cu  = (lin & 15) * 4;
            uint32_t off = (uint32_t)((cu >> 3) * 1024 + r * 8 + ((cu & 7) ^ SW(r)));
            CP16(smb + 4u * off, qp + (size_t)r * Cdim + cu * 2);
        }
    }
    asm volatile("cp.async.commit_group;" ::: "memory");

    const int ntiles = (qbase >> 6) + 2;

    auto loadK = [&](int s, int kb) {
        const __half* kp = k + headoff + (size_t)kb * Cdim;
        uint32_t base = smb + 4u * (uint32_t)(KS_OFF + s * KS_STRIDE);
#pragma unroll
        for (int l = 0; l < 4; ++l) {
            int lin = l * 256 + tid;
            int r   = lin >> 4;
            int cu  = (lin & 15) * 4;
            uint32_t off = (uint32_t)((cu >> 3) * 512 + r * 8 + ((cu & 7) ^ SW(r)));
            CP16(base + 4u * off, kp + (size_t)r * Cdim + cu * 2);
        }
    };
    loadK(0, 0);
    asm volatile("cp.async.commit_group;" ::: "memory");

    // ---- V prefetch to registers (one tile ahead): 4 x 16B per thread ----
    uint4 vreg[4];
    auto ldgV = [&](int kb) {
        const __half* vp = v + headoff + (size_t)kb * Cdim;
#pragma unroll
        for (int l = 0; l < 4; ++l) {
            int idx = l * 256 + tid;
            int kk  = idx & 63;
            int d   = (idx >> 6) * 8;
            vreg[l] = *(const uint4*)(vp + (size_t)kk * Cdim + d);
        }
    };
    ldgV(0);

    const int rq  = w * 16 + g;
    const int a0q = (rq << 3) + (t ^ SW(rq));
    int rowB[8];
#pragma unroll
    for (int ni = 0; ni < 8; ++ni) {
        int nr = ni * 8 + g;
        rowB[ni] = (nr << 3) + (t ^ SW(nr));
    }
    const int pbase0 = P_OFF + w * 512 + g * 32;   // q=g row; q=g+8 -> +256
    const int pxor   = g << 2;

    float oacc[16][4];
#pragma unroll
    for (int i = 0; i < 16; ++i)
#pragma unroll
        for (int x = 0; x < 4; ++x) oacc[i][x] = 0.f;

    float mprev0 = -INFINITY, mprev1 = -INFINITY;
    float l0 = 0.f, l1 = 0.f;
    const int row0 = qbase + rq;
    const int row1 = row0 + 8;

    __half* Vth = (__half*)(smu + VT_OFF);

    for (int kt = 0; kt < ntiles; ++kt) {
        const int sk = kt & 1;
        const int kbase = kt * ABK;
        const uint32_t* Ks = smu + KS_OFF + sk * KS_STRIDE;

        asm volatile("cp.async.wait_group 0;" ::: "memory");
        __syncthreads();                       // K_kt ready; prev readers done

        if (kt + 1 < ntiles) loadK(sk ^ 1, kbase + ABK);
        asm volatile("cp.async.commit_group;" ::: "memory");

        // transpose V regs -> Vt [d][kk] (fp16, stride 72 halves)
#pragma unroll
        for (int l = 0; l < 4; ++l) {
            int idx = l * 256 + tid;
            int kk  = idx & 63;
            int d   = (idx >> 6) * 8;
            uint32_t ws[4] = {vreg[l].x, vreg[l].y, vreg[l].z, vreg[l].w};
#pragma unroll
            for (int c2 = 0; c2 < 4; ++c2) {
                Vth[(d + 2 * c2) * 72 + kk] =
                    __ushort_as_half((unsigned short)(ws[c2] & 0xffffu));
                Vth[(d + 2 * c2 + 1) * 72 + kk] =
                    __ushort_as_half((unsigned short)(ws[c2] >> 16));
            }
        }
        __syncthreads();

        if (kt + 1 < ntiles) ldgV(kbase + ABK);

        // ---- S = Q K^T  (8 k16-steps over D=128) ----
        float sacc[8][4];
#pragma unroll
        for (int ni = 0; ni < 8; ++ni)
#pragma unroll
            for (int x = 0; x < 4; ++x) sacc[ni][x] = 0.f;

#pragma unroll
        for (int ks = 0; ks < 8; ++ks) {
            const uint32_t* Qk = smu + ks * 1024;
            const uint32_t* Kk = Ks + ks * 512;
            uint32_t a[4];
            a[0] = Qk[a0q];
            a[1] = Qk[a0q + 64];
            a[2] = Qk[a0q ^ 4];
            a[3] = Qk[(a0q ^ 4) + 64];
#pragma unroll
            for (int ni = 0; ni < 8; ++ni) {
                uint32_t bb[2];
                bb[0] = Kk[rowB[ni]];
                bb[1] = Kk[rowB[ni] ^ 4];
                MMA_F16(sacc[ni], a, bb);
            }
        }

        // ---- scale + ALiBi + causal; online softmax ----
        float mt0 = -INFINITY, mt1 = -INFINITY;
#pragma unroll
        for (int ni = 0; ni < 8; ++ni) {
            int col = kbase + ni * 8 + 2 * t;
            float al0 = slope * (float)(col - (Tseq - 1));
            float al1 = slope * (float)(col + 1 - (Tseq - 1));
            float v0 = sacc[ni][0] * scale + al0;
            float v1 = sacc[ni][1] * scale + al1;
            float v2 = sacc[ni][2] * scale + al0;
            float v3 = sacc[ni][3] * scale + al1;
            if (col     > row0) v0 = -1e30f;
            if (col + 1 > row0) v1 = -1e30f;
            if (col     > row1) v2 = -1e30f;
            if (col + 1 > row1) v3 = -1e30f;
            sacc[ni][0] = v0; sacc[ni][1] = v1; sacc[ni][2] = v2; sacc[ni][3] = v3;
            mt0 = fmaxf(mt0, fmaxf(v0, v1));
            mt1 = fmaxf(mt1, fmaxf(v2, v3));
        }
        mt0 = fmaxf(mt0, __shfl_xor_sync(0xffffffffu, mt0, 1));
        mt0 = fmaxf(mt0, __shfl_xor_sync(0xffffffffu, mt0, 2));
        mt1 = fmaxf(mt1, __shfl_xor_sync(0xffffffffu, mt1, 1));
        mt1 = fmaxf(mt1, __shfl_xor_sync(0xffffffffu, mt1, 2));
        float mnew0 = fmaxf(mprev0, mt0);
        float mnew1 = fmaxf(mprev1, mt1);
        float corr0 = __expf(mprev0 - mnew0);
        float corr1 = __expf(mprev1 - mnew1);
        float sum0 = 0.f, sum1 = 0.f;
#pragma unroll
        for (int ni = 0; ni < 8; ++ni) {
            float p0 = __expf(sacc[ni][0] - mnew0);
            float p1 = __expf(sacc[ni][1] - mnew0);
            float p2 = __expf(sacc[ni][2] - mnew1);
            float p3 = __expf(sacc[ni][3] - mnew1);
            sum0 += p0 + p1; sum1 += p2 + p3;
            int u = ni * 4 + t;
            *(__half2*)&smu[pbase0 + (u ^ pxor)]       = __floats2half2_rn(p0, p1);
            *(__half2*)&smu[pbase0 + 256 + (u ^ pxor)] = __floats2half2_rn(p2, p3);
        }
        sum0 += __shfl_xor_sync(0xffffffffu, sum0, 1);
        sum0 += __shfl_xor_sync(0xffffffffu, sum0, 2);
        sum1 += __shfl_xor_sync(0xffffffffu, sum1, 1);
        sum1 += __shfl_xor_sync(0xffffffffu, sum1, 2);
        l0 = l0 * corr0 + sum0;
        l1 = l1 * corr1 + sum1;
        mprev0 = mnew0; mprev1 = mnew1;
#pragma unroll
        for (int i = 0; i < 16; ++i) {
            oacc[i][0] *= corr0; oacc[i][1] *= corr0;
            oacc[i][2] *= corr1; oacc[i][3] *= corr1;
        }
        __syncwarp();

        // ---- O += P V  (4 k16-steps over 64 keys) ----
#pragma unroll
        for (int ks = 0; ks < 4; ++ks) {
            uint32_t a[4];
            int ua = (ks * 8 + t) ^ pxor;
            a[0] = smu[pbase0 + ua];
            a[1] = smu[pbase0 + 256 + ua];
            a[2] = smu[pbase0 + (ua ^ 4)];
            a[3] = smu[pbase0 + 256 + (ua ^ 4)];
#pragma unroll
            for (int d = 0; d < 16; ++d) {
                const uint32_t* Vr = smu + VT_OFF + (d * 8 + g) * VT_RSU + ks * 8 + t;
                uint32_t bb[2];
                bb[0] = Vr[0];
                bb[1] = Vr[4];
                MMA_F16(oacc[d], a, bb);
            }
        }
    }

    // ---- epilogue: normalize, fp16 store (feeds final GEMM) ----
    float inv0 = 1.f / l0, inv1 = 1.f / l1;
    __half* op0 = o + headoff + (size_t)row0 * Cdim;
    __half* op1 = o + headoff + (size_t)row1 * Cdim;
#pragma unroll
    for (int d = 0; d < 16; ++d) {
        int col = d * 8 + 2 * t;
        *(__half2*)(op0 + col) = __floats2half2_rn(oacc[d][0] * inv0, oacc[d][1] * inv0);
        *(__half2*)(op1 + col) = __floats2half2_rn(oacc[d][2] * inv1, oacc[d][3] * inv1);
    }
}

// ============================================================================
// Launch
// ============================================================================
extern "C" void kernel_launch(void* const* d_in, const int* in_sizes, int n_in,
                              void* d_out, int out_size)
{
    const float* x  = (const float*)d_in[0];
    const float* Wq = (const float*)d_in[1];
    const float* bq = (const float*)d_in[2];
    const float* Wk = (const float*)d_in[3];
    const float* bk = (const float*)d_in[4];
    const float* Wv = (const float*)d_in[5];
    const float* bv = (const float*)d_in[6];
    const float* Wo = (const float*)d_in[7];
    const float* bo = (const float*)d_in[8];
    float* out = (float*)d_out;

    __half *qp, *kp, *vp, *op, *xh, *wt;
    cudaGetSymbolAddress((void**)&qp, g_q);
    cudaGetSymbolAddress((void**)&kp, g_k);
    cudaGetSymbolAddress((void**)&vp, g_v);
    cudaGetSymbolAddress((void**)&op, g_o);
    cudaGetSymbolAddress((void**)&xh, g_xh);
    cudaGetSymbolAddress((void**)&wt, g_wt);
    __half* wto = wt + 3 * (size_t)Cdim * Cdim;

    cudaFuncSetAttribute(gemm_qkv_kernel,
                         cudaFuncAttributeMaxDynamicSharedMemorySize, GEMM_SMEM);
    cudaFuncSetAttribute(gemm_o_kernel,
                         cudaFuncAttributeMaxDynamicSharedMemorySize, GEMM_SMEM);
    cudaFuncSetAttribute(attn_mma_kernel,
                         cudaFuncAttributeMaxDynamicSharedMemorySize, ATTN_SMEM_BYTES);

    round_h_k<<<(Mrows * Cdim) / 1024, 256>>>(x, xh);
    dim3 tb(32, 8), tg(Cdim / 32, Cdim / 32);
    transpose_h_k<<<tg, tb>>>(Wq, wt);
    transpose_h_k<<<tg, tb>>>(Wk, wt + (size_t)Cdim * Cdim);
    transpose_h_k<<<tg, tb>>>(Wv, wt + 2 * (size_t)Cdim * Cdim);
    transpose_h_k<<<tg, tb>>>(Wo, wto);

    dim3 gq(Cdim / GBN, Mrows / GBM, 3);   // (8, 32, 3)
    gemm_qkv_kernel<<<gq, 256, GEMM_SMEM>>>(xh, wt, bq, bk, bv, qp, kp, vp);

    dim3 ga(Tseq / ABQ, Hh, Bsz);          // (16, 16, 2)
    attn_mma_kernel<<<ga, 256, ATTN_SMEM_BYTES>>>(qp, kp, vp, op);

    dim3 go(Cdim / GBN, Mrows / GBM);      // (8, 32)
    gemm_o_kernel<<<go, 256, GEMM_SMEM>>>(op, wto, bo, out);
}

// round 8
// speedup vs baseline: 5.8239x; 1.1027x over previous
#include <cuda_runtime.h>
#include <cuda_fp16.h>
#include <math.h>
#include <stdint.h>

// Problem constants
#define Bsz  2
#define Tseq 2048
#define Cdim 2048
#define Hh   16
#define Dh   128
#define Mrows (Bsz*Tseq)   // 4096

// -------- scratch (device globals; no allocation allowed) --------
__device__ __half g_q[(size_t)Mrows * Cdim];
__device__ __half g_k[(size_t)Mrows * Cdim];
__device__ __half g_v[(size_t)Mrows * Cdim];
__device__ __half g_o[(size_t)Mrows * Cdim];
__device__ __half g_xh[(size_t)Mrows * Cdim];       // fp16 x
__device__ __half g_wt[4][(size_t)Cdim * Cdim];     // transposed fp16 weights

// ============================================================================
// Helpers
// ============================================================================
__device__ __forceinline__ uint32_t smem_u32(const void* p) {
    uint32_t a;
    asm("{ .reg .u64 t; cvta.to.shared.u64 t, %1; cvt.u32.u64 %0, t; }"
        : "=r"(a) : "l"(p));
    return a;
}

#define CP16(sa, ga) \
    asm volatile("cp.async.cg.shared.global [%0], [%1], 16;" \
                 :: "r"(sa), "l"(ga) : "memory")

#define MMA_F16(c, a0, a1, a2, a3, b0, b1) \
    asm volatile("mma.sync.aligned.m16n8k16.row.col.f32.f16.f16.f32 " \
        "{%0,%1,%2,%3},{%4,%5,%6,%7},{%8,%9},{%0,%1,%2,%3};" \
        : "+f"((c)[0]), "+f"((c)[1]), "+f"((c)[2]), "+f"((c)[3]) \
        : "r"(a0), "r"(a1), "r"(a2), "r"(a3), "r"(b0), "r"(b1))

#define LDSM4(r0, r1, r2, r3, addr) \
    asm volatile("ldmatrix.sync.aligned.m8n8.x4.shared.b16 {%0,%1,%2,%3}, [%4];" \
        : "=r"(r0), "=r"(r1), "=r"(r2), "=r"(r3) : "r"(addr))

#define LDSM4T(r0, r1, r2, r3, addr) \
    asm volatile("ldmatrix.sync.aligned.m8n8.x4.trans.shared.b16 {%0,%1,%2,%3}, [%4];" \
        : "=r"(r0), "=r"(r1), "=r"(r2), "=r"(r3) : "r"(addr))

#define SW(r) ((((r) >> 2) & 1) << 2)

__device__ __forceinline__ uint32_t pack_h2(float lo, float hi) {
    __half2 h = __floats2half2_rn(lo, hi);
    return *reinterpret_cast<uint32_t*>(&h);
}

// ============================================================================
// x -> fp16
// ============================================================================
__global__ __launch_bounds__(256) void round_h_k(
    const float* __restrict__ in, __half* __restrict__ out)
{
    size_t i = ((size_t)blockIdx.x * 256 + threadIdx.x) * 4;
    float4 v = *(const float4*)(in + i);
    *(__half2*)(out + i)     = __floats2half2_rn(v.x, v.y);
    *(__half2*)(out + i + 2) = __floats2half2_rn(v.z, v.w);
}

// ============================================================================
// Transpose 2048x2048 f32 -> fp16, all 4 weights in one launch (z selects)
// ============================================================================
__global__ __launch_bounds__(256) void transpose_h_k(
    const float* __restrict__ w0, const float* __restrict__ w1,
    const float* __restrict__ w2, const float* __restrict__ w3,
    __half* __restrict__ outbase)
{
    __shared__ float t[32][33];
    const int z = blockIdx.z;
    const float* in = (z == 0) ? w0 : (z == 1) ? w1 : (z == 2) ? w2 : w3;
    __half* out = outbase + (size_t)z * Cdim * Cdim;
    const int tx = threadIdx.x, ty = threadIdx.y;
    const int x = blockIdx.x * 32 + tx;
    const int y0 = blockIdx.y * 32;
#pragma unroll
    for (int i = 0; i < 32; i += 8)
        t[ty + i][tx] = in[(size_t)(y0 + ty + i) * Cdim + x];
    __syncthreads();
    const int xo = blockIdx.y * 32 + tx;
    const int yo0 = blockIdx.x * 32;
#pragma unroll
    for (int i = 0; i < 32; i += 8)
        out[(size_t)(yo0 + ty + i) * Cdim + xo] = __float2half_rn(t[tx][ty + i]);
}

// ============================================================================
// fp16 mma.sync GEMM with ldmatrix: C[M,2048] = A @ Bt^T + bias
// CTA 128x256, BK=64 halves, 3-stage cp.async, 8 warps, warp 64x64.
// ============================================================================
#define GBM 128
#define GBN 256
#define GBK 64
#define NST 3
#define A_U32 (GBM * GBK / 2)              // 4096
#define B_U32 (GBN * GBK / 2)              // 8192
#define STAGE_U32 (A_U32 + B_U32)          // 12288
#define STAGE_BYTES (STAGE_U32 * 4)        // 49152
#define GEMM_SMEM (NST * STAGE_BYTES)      // 147456

template<typename OutT>
__device__ __forceinline__ void gemm_body_h(
    const __half* __restrict__ A, const __half* __restrict__ Bt,
    const float* __restrict__ bias, OutT* __restrict__ Cm,
    uint32_t smbase)
{
    const int tid  = threadIdx.x;
    const int lane = tid & 31;
    const int wid  = tid >> 5;
    const int wm   = wid >> 2;       // 0..1
    const int wn   = wid & 3;        // 0..3
    const int m0   = blockIdx.y * GBM;
    const int n0   = blockIdx.x * GBN;
    const int g    = lane >> 2;
    const int t    = lane & 3;
    const int l15  = lane & 15;

    // ldmatrix byte offsets (within a k16-step block)
    uint32_t offA[4], offB[4];
#pragma unroll
    for (int mi = 0; mi < 4; ++mi) {
        int r = wm * 64 + mi * 16 + l15;
        int c = lane >> 4;
        offA[mi] = 4u * (uint32_t)(r * 8 + ((c << 2) ^ SW(r)));
    }
#pragma unroll
    for (int nj = 0; nj < 4; ++nj) {
        int r = wn * 64 + nj * 16 + ((lane >> 4) << 3) + (lane & 7);
        int c = (lane >> 3) & 1;
        offB[nj] = 4u * (uint32_t)(r * 8 + ((c << 2) ^ SW(r)));
    }

    float acc[4][8][4];
#pragma unroll
    for (int mi = 0; mi < 4; ++mi)
#pragma unroll
        for (int ni = 0; ni < 8; ++ni)
#pragma unroll
            for (int x = 0; x < 4; ++x) acc[mi][ni][x] = 0.f;

    auto load_stage = [&](int s, int k0) {
        uint32_t ab = smbase + (uint32_t)s * STAGE_BYTES;
        uint32_t bb = ab + A_U32 * 4;
        const __half* Ap = A  + (size_t)m0 * Cdim + k0;
        const __half* Bp = Bt + (size_t)n0 * Cdim + k0;
#pragma unroll
        for (int i = 0; i < 4; ++i) {
            int lin = i * 256 + tid;
            int r   = lin >> 3;
            int cu  = (lin & 7) * 4;
            uint32_t off = 4u * (uint32_t)((cu >> 3) * 1024 + r * 8 + ((cu & 7) ^ SW(r)));
            CP16(ab + off, Ap + (size_t)r * Cdim + cu * 2);
        }
#pragma unroll
        for (int i = 0; i < 8; ++i) {
            int lin = i * 256 + tid;
            int r   = lin >> 3;
            int cu  = (lin & 7) * 4;
            uint32_t off = 4u * (uint32_t)((cu >> 3) * 2048 + r * 8 + ((cu & 7) ^ SW(r)));
            CP16(bb + off, Bp + (size_t)r * Cdim + cu * 2);
        }
    };

    load_stage(0, 0);
    asm volatile("cp.async.commit_group;" ::: "memory");
    load_stage(1, GBK);
    asm volatile("cp.async.commit_group;" ::: "memory");

    const int NIT = Cdim / GBK;            // 32
    for (int it = 0; it < NIT; ++it) {
        asm volatile("cp.async.wait_group 1;" ::: "memory");
        __syncthreads();

        const int nx = it + 2;
        if (nx < NIT) load_stage(nx % NST, nx * GBK);
        asm volatile("cp.async.commit_group;" ::: "memory");

        uint32_t abase = smbase + (uint32_t)(it % NST) * STAGE_BYTES;
        uint32_t bbase = abase + A_U32 * 4;

#pragma unroll
        for (int ks = 0; ks < 4; ++ks) {
            uint32_t a[4][4], b[4][4];
#pragma unroll
            for (int mi = 0; mi < 4; ++mi)
                LDSM4(a[mi][0], a[mi][1], a[mi][2], a[mi][3],
                      abase + ks * 4096 + offA[mi]);
#pragma unroll
            for (int nj = 0; nj < 4; ++nj)
                LDSM4(b[nj][0], b[nj][1], b[nj][2], b[nj][3],
                      bbase + ks * 8192 + offB[nj]);
#pragma unroll
            for (int mi = 0; mi < 4; ++mi)
#pragma unroll
                for (int nj = 0; nj < 4; ++nj) {
                    MMA_F16(acc[mi][2 * nj],     a[mi][0], a[mi][1], a[mi][2], a[mi][3],
                            b[nj][0], b[nj][1]);
                    MMA_F16(acc[mi][2 * nj + 1], a[mi][0], a[mi][1], a[mi][2], a[mi][3],
                            b[nj][2], b[nj][3]);
                }
        }
    }

#pragma unroll
    for (int mi = 0; mi < 4; ++mi) {
        int r0 = m0 + wm * 64 + mi * 16 + g;
#pragma unroll
        for (int ni = 0; ni < 8; ++ni) {
            int col = n0 + wn * 64 + ni * 8 + 2 * t;
            float2 bb = *(const float2*)(bias + col);
            float v0 = acc[mi][ni][0] + bb.x, v1 = acc[mi][ni][1] + bb.y;
            float v2 = acc[mi][ni][2] + bb.x, v3 = acc[mi][ni][3] + bb.y;
            if (sizeof(OutT) == 2) {
                __half* C = (__half*)Cm;
                *(__half2*)(C + (size_t)r0 * Cdim + col)       = __floats2half2_rn(v0, v1);
                *(__half2*)(C + (size_t)(r0 + 8) * Cdim + col) = __floats2half2_rn(v2, v3);
            } else {
                float* C = (float*)Cm;
                *(float2*)(C + (size_t)r0 * Cdim + col)       = make_float2(v0, v1);
                *(float2*)(C + (size_t)(r0 + 8) * Cdim + col) = make_float2(v2, v3);
            }
        }
    }
}

__global__ __launch_bounds__(256, 1) void gemm_qkv_kernel(
    const __half* __restrict__ A, const __half* __restrict__ WtBase,
    const float* __restrict__ bq, const float* __restrict__ bk,
    const float* __restrict__ bv,
    __half* __restrict__ Cq, __half* __restrict__ Ck, __half* __restrict__ Cv)
{
    extern __shared__ uint32_t smu[];
    const int z = blockIdx.z;
    const __half* Bt  = WtBase + (size_t)z * Cdim * Cdim;
    const float* bias = (z == 0) ? bq : (z == 1) ? bk : bv;
    __half*      Cm   = (z == 0) ? Cq : (z == 1) ? Ck : Cv;
    gemm_body_h<__half>(A, Bt, bias, Cm, smem_u32(smu));
}

__global__ __launch_bounds__(256, 1) void gemm_o_kernel(
    const __half* __restrict__ A, const __half* __restrict__ Bt,
    const float* __restrict__ bias, float* __restrict__ Cm)
{
    extern __shared__ uint32_t smu[];
    gemm_body_h<float>(A, Bt, bias, Cm, smem_u32(smu));
}

// ============================================================================
// fp16 flash attention: ldmatrix fragments, register-direct P, ldmatrix.trans V.
// CTA: 128 queries, 8 warps; key tiles of 64; D=128. smem u32 units:
//   Q [0,8192) | K 2x4096 @8192 | V 2x4096 @16384   (total 98304 B)
// ============================================================================
#define ABQ 128
#define ABK 64
#define KS_OFF   8192
#define KS_STRIDE 4096
#define VS_OFF   16384
#define VS_STRIDE 4096
#define ATTN_U32 (VS_OFF + 2 * VS_STRIDE)      // 24576
#define ATTN_SMEM_BYTES (ATTN_U32 * 4)         // 98304

__global__ __launch_bounds__(256, 1) void attn_mma_kernel(
    const __half* __restrict__ q, const __half* __restrict__ k,
    const __half* __restrict__ v, __half* __restrict__ o)
{
    extern __shared__ uint32_t smu[];
    const uint32_t smb = smem_u32(smu);
    const int tid  = threadIdx.x;
    const int lane = tid & 31;
    const int w    = tid >> 5;
    const int g    = lane >> 2;
    const int t    = lane & 3;
    const int l15  = lane & 15;

    const int qbase = blockIdx.x * ABQ;
    const int h = blockIdx.y;
    const int b = blockIdx.z;
    const float scale = 0.08838834764831845f;           // 1/sqrt(128)
    const float slope = exp2f(-0.5f * (float)(h + 1));  // ALiBi slope, H=16
    const size_t headoff = (size_t)b * Tseq * Cdim + (size_t)h * Dh;

    // ---- Q tile: 128 rows x 64 u32 ----
    {
        const __half* qp = q + headoff + (size_t)qbase * Cdim;
#pragma unroll
        for (int l = 0; l < 8; ++l) {
            int lin = l * 256 + tid;
            int r   = lin >> 4;
            int cu  = (lin & 15) * 4;
            uint32_t off = (uint32_t)((cu >> 3) * 1024 + r * 8 + ((cu & 7) ^ SW(r)));
            CP16(smb + 4u * off, qp + (size_t)r * Cdim + cu * 2);
        }
    }
    asm volatile("cp.async.commit_group;" ::: "memory");

    const int ntiles = (qbase >> 6) + 2;

    // K and V tiles: 64 rows x 64 u32 each, same swizzle
    auto loadKV = [&](int s, int kb) {
        const __half* kp = k + headoff + (size_t)kb * Cdim;
        const __half* vp = v + headoff + (size_t)kb * Cdim;
        uint32_t kbs = smb + 4u * (uint32_t)(KS_OFF + s * KS_STRIDE);
        uint32_t vbs = smb + 4u * (uint32_t)(VS_OFF + s * VS_STRIDE);
#pragma unroll
        for (int l = 0; l < 4; ++l) {
            int lin = l * 256 + tid;
            int r   = lin >> 4;
            int cu  = (lin & 15) * 4;
            uint32_t off = 4u * (uint32_t)((cu >> 3) * 512 + r * 8 + ((cu & 7) ^ SW(r)));
            CP16(kbs + off, kp + (size_t)r * Cdim + cu * 2);
            CP16(vbs + off, vp + (size_t)r * Cdim + cu * 2);
        }
    };
    loadKV(0, 0);
    asm volatile("cp.async.commit_group;" ::: "memory");

    // ldmatrix offsets
    uint32_t offQ;                 // A-frag of Q (warp's 16 rows)
    {
        int r = w * 16 + l15;
        int c = lane >> 4;
        offQ = 4u * (uint32_t)(r * 8 + ((c << 2) ^ SW(r)));
    }
    uint32_t offK[4];              // B-frags of K (64 rows)
#pragma unroll
    for (int nj = 0; nj < 4; ++nj) {
        int r = nj * 16 + ((lane >> 4) << 3) + (lane & 7);
        int c = (lane >> 3) & 1;
        offK[nj] = 4u * (uint32_t)(r * 8 + ((c << 2) ^ SW(r)));
    }
    uint32_t offV;                 // trans B-frags of V: + dj*2048 + ks*512 bytes
    {
        int p = lane >> 4;
        offV = 4u * (uint32_t)(l15 * 8 + ((p << 2) ^ SW(l15)));
    }

    float oacc[16][4];
#pragma unroll
    for (int i = 0; i < 16; ++i)
#pragma unroll
        for (int x = 0; x < 4; ++x) oacc[i][x] = 0.f;

    float mprev0 = -INFINITY, mprev1 = -INFINITY;
    float l0 = 0.f, l1 = 0.f;
    const int row0 = qbase + w * 16 + g;
    const int row1 = row0 + 8;

    for (int kt = 0; kt < ntiles; ++kt) {
        const int sk = kt & 1;
        const int kbase = kt * ABK;
        const uint32_t kbs = smb + 4u * (uint32_t)(KS_OFF + sk * KS_STRIDE);
        const uint32_t vbs = smb + 4u * (uint32_t)(VS_OFF + sk * VS_STRIDE);

        asm volatile("cp.async.wait_group 0;" ::: "memory");
        __syncthreads();                       // K/V_kt ready; prev stage readers done

        if (kt + 1 < ntiles) loadKV(sk ^ 1, kbase + ABK);
        asm volatile("cp.async.commit_group;" ::: "memory");

        // ---- S = Q K^T  (8 k16-steps over D=128) ----
        float sacc[8][4];
#pragma unroll
        for (int ni = 0; ni < 8; ++ni)
#pragma unroll
            for (int x = 0; x < 4; ++x) sacc[ni][x] = 0.f;

#pragma unroll
        for (int ks = 0; ks < 8; ++ks) {
            uint32_t a0, a1, a2, a3;
            LDSM4(a0, a1, a2, a3, smb + ks * 4096 + offQ);
#pragma unroll
            for (int nj = 0; nj < 4; ++nj) {
                uint32_t b0, b1, b2, b3;
                LDSM4(b0, b1, b2, b3, kbs + ks * 2048 + offK[nj]);
                MMA_F16(sacc[2 * nj],     a0, a1, a2, a3, b0, b1);
                MMA_F16(sacc[2 * nj + 1], a0, a1, a2, a3, b2, b3);
            }
        }

        // ---- scale + ALiBi + causal; online softmax (in registers) ----
        float mt0 = -INFINITY, mt1 = -INFINITY;
#pragma unroll
        for (int ni = 0; ni < 8; ++ni) {
            int col = kbase + ni * 8 + 2 * t;
            float al0 = slope * (float)(col - (Tseq - 1));
            float al1 = slope * (float)(col + 1 - (Tseq - 1));
            float v0 = sacc[ni][0] * scale + al0;
            float v1 = sacc[ni][1] * scale + al1;
            float v2 = sacc[ni][2] * scale + al0;
            float v3 = sacc[ni][3] * scale + al1;
            if (col     > row0) v0 = -1e30f;
            if (col + 1 > row0) v1 = -1e30f;
            if (col     > row1) v2 = -1e30f;
            if (col + 1 > row1) v3 = -1e30f;
            sacc[ni][0] = v0; sacc[ni][1] = v1; sacc[ni][2] = v2; sacc[ni][3] = v3;
            mt0 = fmaxf(mt0, fmaxf(v0, v1));
            mt1 = fmaxf(mt1, fmaxf(v2, v3));
        }
        mt0 = fmaxf(mt0, __shfl_xor_sync(0xffffffffu, mt0, 1));
        mt0 = fmaxf(mt0, __shfl_xor_sync(0xffffffffu, mt0, 2));
        mt1 = fmaxf(mt1, __shfl_xor_sync(0xffffffffu, mt1, 1));
        mt1 = fmaxf(mt1, __shfl_xor_sync(0xffffffffu, mt1, 2));
        float mnew0 = fmaxf(mprev0, mt0);
        float mnew1 = fmaxf(mprev1, mt1);
        float corr0 = __expf(mprev0 - mnew0);
        float corr1 = __expf(mprev1 - mnew1);
        float sum0 = 0.f, sum1 = 0.f;
#pragma unroll
        for (int ni = 0; ni < 8; ++ni) {
            float p0 = __expf(sacc[ni][0] - mnew0);
            float p1 = __expf(sacc[ni][1] - mnew0);
            float p2 = __expf(sacc[ni][2] - mnew1);
            float p3 = __expf(sacc[ni][3] - mnew1);
            sum0 += p0 + p1; sum1 += p2 + p3;
            sacc[ni][0] = p0; sacc[ni][1] = p1; sacc[ni][2] = p2; sacc[ni][3] = p3;
        }
        sum0 += __shfl_xor_sync(0xffffffffu, sum0, 1);
        sum0 += __shfl_xor_sync(0xffffffffu, sum0, 2);
        sum1 += __shfl_xor_sync(0xffffffffu, sum1, 1);
        sum1 += __shfl_xor_sync(0xffffffffu, sum1, 2);
        l0 = l0 * corr0 + sum0;
        l1 = l1 * corr1 + sum1;
        mprev0 = mnew0; mprev1 = mnew1;
#pragma unroll
        for (int i = 0; i < 16; ++i) {
            oacc[i][0] *= corr0; oacc[i][1] *= corr0;
            oacc[i][2] *= corr1; oacc[i][3] *= corr1;
        }

        // ---- O += P V : P direct from registers, V via ldmatrix.trans ----
#pragma unroll
        for (int ks = 0; ks < 4; ++ks) {
            // A-frag of P for keys 16ks..16ks+15 (C-frag -> A-frag identity)
            uint32_t pa0 = pack_h2(sacc[2 * ks][0],     sacc[2 * ks][1]);
            uint32_t pa1 = pack_h2(sacc[2 * ks][2],     sacc[2 * ks][3]);
            uint32_t pa2 = pack_h2(sacc[2 * ks + 1][0], sacc[2 * ks + 1][1]);
            uint32_t pa3 = pack_h2(sacc[2 * ks + 1][2], sacc[2 * ks + 1][3]);
#pragma unroll
            for (int dj = 0; dj < 8; ++dj) {
                uint32_t b0, b1, b2, b3;
                LDSM4T(b0, b1, b2, b3, vbs + dj * 2048 + ks * 512 + offV);
                MMA_F16(oacc[2 * dj],     pa0, pa1, pa2, pa3, b0, b1);
                MMA_F16(oacc[2 * dj + 1], pa0, pa1, pa2, pa3, b2, b3);
            }
        }
    }

    // ---- epilogue: normalize, fp16 store (feeds final GEMM) ----
    float inv0 = 1.f / l0, inv1 = 1.f / l1;
    __half* op0 = o + headoff + (size_t)row0 * Cdim;
    __half* op1 = o + headoff + (size_t)row1 * Cdim;
#pragma unroll
    for (int d = 0; d < 16; ++d) {
        int col = d * 8 + 2 * t;
        *(__half2*)(op0 + col) = __floats2half2_rn(oacc[d][0] * inv0, oacc[d][1] * inv0);
        *(__half2*)(op1 + col) = __floats2half2_rn(oacc[d][2] * inv1, oacc[d][3] * inv1);
    }
}

// ============================================================================
// Launch
// ============================================================================
extern "C" void kernel_launch(void* const* d_in, const int* in_sizes, int n_in,
                              void* d_out, int out_size)
{
    const float* x  = (const float*)d_in[0];
    const float* Wq = (const float*)d_in[1];
    const float* bq = (const float*)d_in[2];
    const float* Wk = (const float*)d_in[3];
    const float* bk = (const float*)d_in[4];
    const float* Wv = (const float*)d_in[5];
    const float* bv = (const float*)d_in[6];
    const float* Wo = (const float*)d_in[7];
    const float* bo = (const float*)d_in[8];
    float* out = (float*)d_out;

    __half *qp, *kp, *vp, *op, *xh, *wt;
    cudaGetSymbolAddress((void**)&qp, g_q);
    cudaGetSymbolAddress((void**)&kp, g_k);
    cudaGetSymbolAddress((void**)&vp, g_v);
    cudaGetSymbolAddress((void**)&op, g_o);
    cudaGetSymbolAddress((void**)&xh, g_xh);
    cudaGetSymbolAddress((void**)&wt, g_wt);
    __half* wto = wt + 3 * (size_t)Cdim * Cdim;

    cudaFuncSetAttribute(gemm_qkv_kernel,
                         cudaFuncAttributeMaxDynamicSharedMemorySize, GEMM_SMEM);
    cudaFuncSetAttribute(gemm_o_kernel,
                         cudaFuncAttributeMaxDynamicSharedMemorySize, GEMM_SMEM);
    cudaFuncSetAttribute(attn_mma_kernel,
                         cudaFuncAttributeMaxDynamicSharedMemorySize, ATTN_SMEM_BYTES);

    round_h_k<<<(Mrows * Cdim) / 1024, 256>>>(x, xh);
    dim3 tb(32, 8), tg(Cdim / 32, Cdim / 32, 4);
    transpose_h_k<<<tg, tb>>>(Wq, Wk, Wv, Wo, wt);

    dim3 gq(Cdim / GBN, Mrows / GBM, 3);   // (8, 32, 3)
    gemm_qkv_kernel<<<gq, 256, GEMM_SMEM>>>(xh, wt, bq, bk, bv, qp, kp, vp);

    dim3 ga(Tseq / ABQ, Hh, Bsz);          // (16, 16, 2)
    attn_mma_kernel<<<ga, 256, ATTN_SMEM_BYTES>>>(qp, kp, vp, op);

    dim3 go(Cdim / GBN, Mrows / GBM);      // (8, 32)
    gemm_o_kernel<<<go, 256, GEMM_SMEM>>>(op, wto, bo, out);
}

// round 9
// speedup vs baseline: 5.9723x; 1.0255x over previous
#include <cuda_runtime.h>
#include <cuda_fp16.h>
#include <math.h>
#include <stdint.h>

// Problem constants
#define Bsz  2
#define Tseq 2048
#define Cdim 2048
#define Hh   16
#define Dh   128
#define Mrows (Bsz*Tseq)   // 4096

// -------- scratch (device globals; no allocation allowed) --------
__device__ __half g_q[(size_t)Mrows * Cdim];
__device__ __half g_k[(size_t)Mrows * Cdim];
__device__ __half g_v[(size_t)Mrows * Cdim];
__device__ __half g_o[(size_t)Mrows * Cdim];
__device__ __half g_xh[(size_t)Mrows * Cdim];       // fp16 x
__device__ __half g_wt[4][(size_t)Cdim * Cdim];     // transposed fp16 weights

// ============================================================================
// Helpers
// ============================================================================
__device__ __forceinline__ uint32_t smem_u32(const void* p) {
    uint32_t a;
    asm("{ .reg .u64 t; cvta.to.shared.u64 t, %1; cvt.u32.u64 %0, t; }"
        : "=r"(a) : "l"(p));
    return a;
}

#define CP16(sa, ga) \
    asm volatile("cp.async.cg.shared.global [%0], [%1], 16;" \
                 :: "r"(sa), "l"(ga) : "memory")

#define MMA_F16(c, a0, a1, a2, a3, b0, b1) \
    asm volatile("mma.sync.aligned.m16n8k16.row.col.f32.f16.f16.f32 " \
        "{%0,%1,%2,%3},{%4,%5,%6,%7},{%8,%9},{%0,%1,%2,%3};" \
        : "+f"((c)[0]), "+f"((c)[1]), "+f"((c)[2]), "+f"((c)[3]) \
        : "r"(a0), "r"(a1), "r"(a2), "r"(a3), "r"(b0), "r"(b1))

#define LDSM4(r0, r1, r2, r3, addr) \
    asm volatile("ldmatrix.sync.aligned.m8n8.x4.shared.b16 {%0,%1,%2,%3}, [%4];" \
        : "=r"(r0), "=r"(r1), "=r"(r2), "=r"(r3) : "r"(addr))

#define LDSM4T(r0, r1, r2, r3, addr) \
    asm volatile("ldmatrix.sync.aligned.m8n8.x4.trans.shared.b16 {%0,%1,%2,%3}, [%4];" \
        : "=r"(r0), "=r"(r1), "=r"(r2), "=r"(r3) : "r"(addr))

#define SW(r) ((((r) >> 2) & 1) << 2)

__device__ __forceinline__ uint32_t pack_h2(float lo, float hi) {
    __half2 h = __floats2half2_rn(lo, hi);
    return *reinterpret_cast<uint32_t*>(&h);
}

// ============================================================================
// x -> fp16
// ============================================================================
__global__ __launch_bounds__(256) void round_h_k(
    const float* __restrict__ in, __half* __restrict__ out)
{
    size_t i = ((size_t)blockIdx.x * 256 + threadIdx.x) * 4;
    float4 v = *(const float4*)(in + i);
    *(__half2*)(out + i)     = __floats2half2_rn(v.x, v.y);
    *(__half2*)(out + i + 2) = __floats2half2_rn(v.z, v.w);
}

// ============================================================================
// Transpose 2048x2048 f32 -> fp16, all 4 weights in one launch (z selects)
// ============================================================================
__global__ __launch_bounds__(256) void transpose_h_k(
    const float* __restrict__ w0, const float* __restrict__ w1,
    const float* __restrict__ w2, const float* __restrict__ w3,
    __half* __restrict__ outbase)
{
    __shared__ float t[32][33];
    const int z = blockIdx.z;
    const float* in = (z == 0) ? w0 : (z == 1) ? w1 : (z == 2) ? w2 : w3;
    __half* out = outbase + (size_t)z * Cdim * Cdim;
    const int tx = threadIdx.x, ty = threadIdx.y;
    const int x = blockIdx.x * 32 + tx;
    const int y0 = blockIdx.y * 32;
#pragma unroll
    for (int i = 0; i < 32; i += 8)
        t[ty + i][tx] = in[(size_t)(y0 + ty + i) * Cdim + x];
    __syncthreads();
    const int xo = blockIdx.y * 32 + tx;
    const int yo0 = blockIdx.x * 32;
#pragma unroll
    for (int i = 0; i < 32; i += 8)
        out[(size_t)(yo0 + ty + i) * Cdim + xo] = __float2half_rn(t[tx][ty + i]);
}

// ============================================================================
// fp16 mma.sync GEMM with ldmatrix: C[M,2048] = A @ Bt^T + bias
// CTA 128x256, BK=64 halves, 3-stage cp.async, 16 warps (2x8), warp 64x32.
// ============================================================================
#define GBM 128
#define GBN 256
#define GBK 64
#define NST 3
#define GTH 512
#define A_U32 (GBM * GBK / 2)              // 4096
#define B_U32 (GBN * GBK / 2)              // 8192
#define STAGE_U32 (A_U32 + B_U32)          // 12288
#define STAGE_BYTES (STAGE_U32 * 4)        // 49152
#define GEMM_SMEM (NST * STAGE_BYTES)      // 147456

template<typename OutT>
__device__ __forceinline__ void gemm_body_h(
    const __half* __restrict__ A, const __half* __restrict__ Bt,
    const float* __restrict__ bias, OutT* __restrict__ Cm,
    uint32_t smbase)
{
    const int tid  = threadIdx.x;
    const int lane = tid & 31;
    const int wid  = tid >> 5;
    const int wm   = wid >> 3;       // 0..1
    const int wn   = wid & 7;        // 0..7
    const int m0   = blockIdx.y * GBM;
    const int n0   = blockIdx.x * GBN;
    const int g    = lane >> 2;
    const int t    = lane & 3;
    const int l15  = lane & 15;

    // ldmatrix byte offsets (within a k16-step block)
    uint32_t offA[4], offB[2];
#pragma unroll
    for (int mi = 0; mi < 4; ++mi) {
        int r = wm * 64 + mi * 16 + l15;
        int c = lane >> 4;
        offA[mi] = 4u * (uint32_t)(r * 8 + ((c << 2) ^ SW(r)));
    }
#pragma unroll
    for (int nj = 0; nj < 2; ++nj) {
        int r = wn * 32 + nj * 16 + ((lane >> 4) << 3) + (lane & 7);
        int c = (lane >> 3) & 1;
        offB[nj] = 4u * (uint32_t)(r * 8 + ((c << 2) ^ SW(r)));
    }

    float acc[4][4][4];
#pragma unroll
    for (int mi = 0; mi < 4; ++mi)
#pragma unroll
        for (int ni = 0; ni < 4; ++ni)
#pragma unroll
            for (int x = 0; x < 4; ++x) acc[mi][ni][x] = 0.f;

    auto load_stage = [&](int s, int k0) {
        uint32_t ab = smbase + (uint32_t)s * STAGE_BYTES;
        uint32_t bb = ab + A_U32 * 4;
        const __half* Ap = A  + (size_t)m0 * Cdim + k0;
        const __half* Bp = Bt + (size_t)n0 * Cdim + k0;
#pragma unroll
        for (int i = 0; i < 2; ++i) {          // A: 128 rows x 8 chunks
            int lin = i * GTH + tid;
            int r   = lin >> 3;
            int cu  = (lin & 7) * 4;
            uint32_t off = 4u * (uint32_t)((cu >> 3) * 1024 + r * 8 + ((cu & 7) ^ SW(r)));
            CP16(ab + off, Ap + (size_t)r * Cdim + cu * 2);
        }
#pragma unroll
        for (int i = 0; i < 4; ++i) {          // B: 256 rows x 8 chunks
            int lin = i * GTH + tid;
            int r   = lin >> 3;
            int cu  = (lin & 7) * 4;
            uint32_t off = 4u * (uint32_t)((cu >> 3) * 2048 + r * 8 + ((cu & 7) ^ SW(r)));
            CP16(bb + off, Bp + (size_t)r * Cdim + cu * 2);
        }
    };

    load_stage(0, 0);
    asm volatile("cp.async.commit_group;" ::: "memory");
    load_stage(1, GBK);
    asm volatile("cp.async.commit_group;" ::: "memory");

    const int NIT = Cdim / GBK;            // 32
    for (int it = 0; it < NIT; ++it) {
        asm volatile("cp.async.wait_group 1;" ::: "memory");
        __syncthreads();

        const int nx = it + 2;
        if (nx < NIT) load_stage(nx % NST, nx * GBK);
        asm volatile("cp.async.commit_group;" ::: "memory");

        uint32_t abase = smbase + (uint32_t)(it % NST) * STAGE_BYTES;
        uint32_t bbase = abase + A_U32 * 4;

#pragma unroll
        for (int ks = 0; ks < 4; ++ks) {
            uint32_t a[4][4], b[2][4];
#pragma unroll
            for (int mi = 0; mi < 4; ++mi)
                LDSM4(a[mi][0], a[mi][1], a[mi][2], a[mi][3],
                      abase + ks * 4096 + offA[mi]);
#pragma unroll
            for (int nj = 0; nj < 2; ++nj)
                LDSM4(b[nj][0], b[nj][1], b[nj][2], b[nj][3],
                      bbase + ks * 8192 + offB[nj]);
#pragma unroll
            for (int mi = 0; mi < 4; ++mi)
#pragma unroll
                for (int nj = 0; nj < 2; ++nj) {
                    MMA_F16(acc[mi][2 * nj],     a[mi][0], a[mi][1], a[mi][2], a[mi][3],
                            b[nj][0], b[nj][1]);
                    MMA_F16(acc[mi][2 * nj + 1], a[mi][0], a[mi][1], a[mi][2], a[mi][3],
                            b[nj][2], b[nj][3]);
                }
        }
    }

#pragma unroll
    for (int mi = 0; mi < 4; ++mi) {
        int r0 = m0 + wm * 64 + mi * 16 + g;
#pragma unroll
        for (int ni = 0; ni < 4; ++ni) {
            int col = n0 + wn * 32 + ni * 8 + 2 * t;
            float2 bb = *(const float2*)(bias + col);
            float v0 = acc[mi][ni][0] + bb.x, v1 = acc[mi][ni][1] + bb.y;
            float v2 = acc[mi][ni][2] + bb.x, v3 = acc[mi][ni][3] + bb.y;
            if (sizeof(OutT) == 2) {
                __half* C = (__half*)Cm;
                *(__half2*)(C + (size_t)r0 * Cdim + col)       = __floats2half2_rn(v0, v1);
                *(__half2*)(C + (size_t)(r0 + 8) * Cdim + col) = __floats2half2_rn(v2, v3);
            } else {
                float* C = (float*)Cm;
                *(float2*)(C + (size_t)r0 * Cdim + col)       = make_float2(v0, v1);
                *(float2*)(C + (size_t)(r0 + 8) * Cdim + col) = make_float2(v2, v3);
            }
        }
    }
}

__global__ __launch_bounds__(GTH, 1) void gemm_qkv_kernel(
    const __half* __restrict__ A, const __half* __restrict__ WtBase,
    const float* __restrict__ bq, const float* __restrict__ bk,
    const float* __restrict__ bv,
    __half* __restrict__ Cq, __half* __restrict__ Ck, __half* __restrict__ Cv)
{
    extern __shared__ uint32_t smu[];
    const int z = blockIdx.z;
    const __half* Bt  = WtBase + (size_t)z * Cdim * Cdim;
    const float* bias = (z == 0) ? bq : (z == 1) ? bk : bv;
    __half*      Cm   = (z == 0) ? Cq : (z == 1) ? Ck : Cv;
    gemm_body_h<__half>(A, Bt, bias, Cm, smem_u32(smu));
}

__global__ __launch_bounds__(GTH, 1) void gemm_o_kernel(
    const __half* __restrict__ A, const __half* __restrict__ Bt,
    const float* __restrict__ bias, float* __restrict__ Cm)
{
    extern __shared__ uint32_t smu[];
    gemm_body_h<float>(A, Bt, bias, Cm, smem_u32(smu));
}

// ============================================================================
// fp16 flash attention: hoisted Q fragments, register-direct P, ldmatrix.trans V.
// CTA: 128 queries, 8 warps; key tiles of 64; D=128. smem u32 units:
//   Q [0,8192) | K 2x4096 @8192 | V 2x4096 @16384   (total 98304 B)
// Grid reversed: longest (largest qbase) CTAs launch first.
// ============================================================================
#define ABQ 128
#define ABK 64
#define KS_OFF   8192
#define KS_STRIDE 4096
#define VS_OFF   16384
#define VS_STRIDE 4096
#define ATTN_U32 (VS_OFF + 2 * VS_STRIDE)      // 24576
#define ATTN_SMEM_BYTES (ATTN_U32 * 4)         // 98304

__global__ __launch_bounds__(256, 1) void attn_mma_kernel(
    const __half* __restrict__ q, const __half* __restrict__ k,
    const __half* __restrict__ v, __half* __restrict__ o)
{
    extern __shared__ uint32_t smu[];
    const uint32_t smb = smem_u32(smu);
    const int tid  = threadIdx.x;
    const int lane = tid & 31;
    const int w    = tid >> 5;
    const int g    = lane >> 2;
    const int t    = lane & 3;
    const int l15  = lane & 15;

    const int qbase = (gridDim.x - 1 - blockIdx.x) * ABQ;   // long CTAs first
    const int h = blockIdx.y;
    const int b = blockIdx.z;
    const float scale = 0.08838834764831845f;           // 1/sqrt(128)
    const float slope = exp2f(-0.5f * (float)(h + 1));  // ALiBi slope, H=16
    const size_t headoff = (size_t)b * Tseq * Cdim + (size_t)h * Dh;

    // ---- Q tile: 128 rows x 64 u32 ----
    {
        const __half* qp = q + headoff + (size_t)qbase * Cdim;
#pragma unroll
        for (int l = 0; l < 8; ++l) {
            int lin = l * 256 + tid;
            int r   = lin >> 4;
            int cu  = (lin & 15) * 4;
            uint32_t off = (uint32_t)((cu >> 3) * 1024 + r * 8 + ((cu & 7) ^ SW(r)));
            CP16(smb + 4u * off, qp + (size_t)r * Cdim + cu * 2);
        }
    }

    const int ntiles = (qbase >> 6) + 2;

    // K and V tiles: 64 rows x 64 u32 each, same swizzle
    auto loadKV = [&](int s, int kb) {
        const __half* kp = k + headoff + (size_t)kb * Cdim;
        const __half* vp = v + headoff + (size_t)kb * Cdim;
        uint32_t kbs = smb + 4u * (uint32_t)(KS_OFF + s * KS_STRIDE);
        uint32_t vbs = smb + 4u * (uint32_t)(VS_OFF + s * VS_STRIDE);
#pragma unroll
        for (int l = 0; l < 4; ++l) {
            int lin = l * 256 + tid;
            int r   = lin >> 4;
            int cu  = (lin & 15) * 4;
            uint32_t off = 4u * (uint32_t)((cu >> 3) * 512 + r * 8 + ((cu & 7) ^ SW(r)));
            CP16(kbs + off, kp + (size_t)r * Cdim + cu * 2);
            CP16(vbs + off, vp + (size_t)r * Cdim + cu * 2);
        }
    };
    loadKV(0, 0);
    asm volatile("cp.async.commit_group;" ::: "memory");

    // ldmatrix offsets
    uint32_t offQ;
    {
        int r = w * 16 + l15;
        int c = lane >> 4;
        offQ = 4u * (uint32_t)(r * 8 + ((c << 2) ^ SW(r)));
    }
    uint32_t offK[4];
#pragma unroll
    for (int nj = 0; nj < 4; ++nj) {
        int r = nj * 16 + ((lane >> 4) << 3) + (lane & 7);
        int c = (lane >> 3) & 1;
        offK[nj] = 4u * (uint32_t)(r * 8 + ((c << 2) ^ SW(r)));
    }
    uint32_t offV;
    {
        int p = lane >> 4;
        offV = 4u * (uint32_t)(l15 * 8 + ((p << 2) ^ SW(l15)));
    }

    // ---- wait for Q + K/V(0); hoist Q fragments (invariant over key tiles) ----
    asm volatile("cp.async.wait_group 0;" ::: "memory");
    __syncthreads();
    uint32_t qa[8][4];
#pragma unroll
    for (int ks = 0; ks < 8; ++ks)
        LDSM4(qa[ks][0], qa[ks][1], qa[ks][2], qa[ks][3], smb + ks * 4096 + offQ);

    float oacc[16][4];
#pragma unroll
    for (int i = 0; i < 16; ++i)
#pragma unroll
        for (int x = 0; x < 4; ++x) oacc[i][x] = 0.f;

    float mprev0 = -INFINITY, mprev1 = -INFINITY;
    float l0 = 0.f, l1 = 0.f;
    const int row0 = qbase + w * 16 + g;
    const int row1 = row0 + 8;

    for (int kt = 0; kt < ntiles; ++kt) {
        const int sk = kt & 1;
        const int kbase = kt * ABK;
        const uint32_t kbs = smb + 4u * (uint32_t)(KS_OFF + sk * KS_STRIDE);
        const uint32_t vbs = smb + 4u * (uint32_t)(VS_OFF + sk * VS_STRIDE);

        // issue next K/V load before compute
        if (kt + 1 < ntiles) {
            loadKV(sk ^ 1, kbase + ABK);
            asm volatile("cp.async.commit_group;" ::: "memory");
        }

        // ---- S = Q K^T  (8 k16-steps over D=128) ----
        float sacc[8][4];
#pragma unroll
        for (int ni = 0; ni < 8; ++ni)
#pragma unroll
            for (int x = 0; x < 4; ++x) sacc[ni][x] = 0.f;

#pragma unroll
        for (int ks = 0; ks < 8; ++ks) {
#pragma unroll
            for (int nj = 0; nj < 4; ++nj) {
                uint32_t b0, b1, b2, b3;
                LDSM4(b0, b1, b2, b3, kbs + ks * 2048 + offK[nj]);
                MMA_F16(sacc[2 * nj],     qa[ks][0], qa[ks][1], qa[ks][2], qa[ks][3], b0, b1);
                MMA_F16(sacc[2 * nj + 1], qa[ks][0], qa[ks][1], qa[ks][2], qa[ks][3], b2, b3);
            }
        }

        // ---- scale + ALiBi + causal; online softmax (in registers) ----
        float mt0 = -INFINITY, mt1 = -INFINITY;
#pragma unroll
        for (int ni = 0; ni < 8; ++ni) {
            int col = kbase + ni * 8 + 2 * t;
            float al0 = slope * (float)(col - (Tseq - 1));
            float al1 = slope * (float)(col + 1 - (Tseq - 1));
            float v0 = sacc[ni][0] * scale + al0;
            float v1 = sacc[ni][1] * scale + al1;
            float v2 = sacc[ni][2] * scale + al0;
            float v3 = sacc[ni][3] * scale + al1;
            if (col     > row0) v0 = -1e30f;
            if (col + 1 > row0) v1 = -1e30f;
            if (col     > row1) v2 = -1e30f;
            if (col + 1 > row1) v3 = -1e30f;
            sacc[ni][0] = v0; sacc[ni][1] = v1; sacc[ni][2] = v2; sacc[ni][3] = v3;
            mt0 = fmaxf(mt0, fmaxf(v0, v1));
            mt1 = fmaxf(mt1, fmaxf(v2, v3));
        }
        mt0 = fmaxf(mt0, __shfl_xor_sync(0xffffffffu, mt0, 1));
        mt0 = fmaxf(mt0, __shfl_xor_sync(0xffffffffu, mt0, 2));
        mt1 = fmaxf(mt1, __shfl_xor_sync(0xffffffffu, mt1, 1));
        mt1 = fmaxf(mt1, __shfl_xor_sync(0xffffffffu, mt1, 2));
        float mnew0 = fmaxf(mprev0, mt0);
        float mnew1 = fmaxf(mprev1, mt1);
        float corr0 = __expf(mprev0 - mnew0);
        float corr1 = __expf(mprev1 - mnew1);
        float sum0 = 0.f, sum1 = 0.f;
#pragma unroll
        for (int ni = 0; ni < 8; ++ni) {
            float p0 = __expf(sacc[ni][0] - mnew0);
            float p1 = __expf(sacc[ni][1] - mnew0);
            float p2 = __expf(sacc[ni][2] - mnew1);
            float p3 = __expf(sacc[ni][3] - mnew1);
            sum0 += p0 + p1; sum1 += p2 + p3;
            sacc[ni][0] = p0; sacc[ni][1] = p1; sacc[ni][2] = p2; sacc[ni][3] = p3;
        }
        sum0 += __shfl_xor_sync(0xffffffffu, sum0, 1);
        sum0 += __shfl_xor_sync(0xffffffffu, sum0, 2);
        sum1 += __shfl_xor_sync(0xffffffffu, sum1, 1);
        sum1 += __shfl_xor_sync(0xffffffffu, sum1, 2);
        l0 = l0 * corr0 + sum0;
        l1 = l1 * corr1 + sum1;
        mprev0 = mnew0; mprev1 = mnew1;
#pragma unroll
        for (int i = 0; i < 16; ++i) {
            oacc[i][0] *= corr0; oacc[i][1] *= corr0;
            oacc[i][2] *= corr1; oacc[i][3] *= corr1;
        }

        // ---- O += P V : P direct from registers, V via ldmatrix.trans ----
#pragma unroll
        for (int ks = 0; ks < 4; ++ks) {
            uint32_t pa0 = pack_h2(sacc[2 * ks][0],     sacc[2 * ks][1]);
            uint32_t pa1 = pack_h2(sacc[2 * ks][2],     sacc[2 * ks][3]);
            uint32_t pa2 = pack_h2(sacc[2 * ks + 1][0], sacc[2 * ks + 1][1]);
            uint32_t pa3 = pack_h2(sacc[2 * ks + 1][2], sacc[2 * ks + 1][3]);
#pragma unroll
            for (int dj = 0; dj < 8; ++dj) {
                uint32_t b0, b1, b2, b3;
                LDSM4T(b0, b1, b2, b3, vbs + dj * 2048 + ks * 512 + offV);
                MMA_F16(oacc[2 * dj],     pa0, pa1, pa2, pa3, b0, b1);
                MMA_F16(oacc[2 * dj + 1], pa0, pa1, pa2, pa3, b2, b3);
            }
        }

        // ---- wait next K/V; also fences smem reuse across warps ----
        if (kt + 1 < ntiles) {
            asm volatile("cp.async.wait_group 0;" ::: "memory");
            __syncthreads();
        }
    }

    // ---- epilogue: normalize, fp16 store (feeds final GEMM) ----
    float inv0 = 1.f / l0, inv1 = 1.f / l1;
    __half* op0 = o + headoff + (size_t)row0 * Cdim;
    __half* op1 = o + headoff + (size_t)row1 * Cdim;
#pragma unroll
    for (int d = 0; d < 16; ++d) {
        int col = d * 8 + 2 * t;
        *(__half2*)(op0 + col) = __floats2half2_rn(oacc[d][0] * inv0, oacc[d][1] * inv0);
        *(__half2*)(op1 + col) = __floats2half2_rn(oacc[d][2] * inv1, oacc[d][3] * inv1);
    }
}

// ============================================================================
// Launch
// ============================================================================
extern "C" void kernel_launch(void* const* d_in, const int* in_sizes, int n_in,
                              void* d_out, int out_size)
{
    const float* x  = (const float*)d_in[0];
    const float* Wq = (const float*)d_in[1];
    const float* bq = (const float*)d_in[2];
    const float* Wk = (const float*)d_in[3];
    const float* bk = (const float*)d_in[4];
    const float* Wv = (const float*)d_in[5];
    const float* bv = (const float*)d_in[6];
    const float* Wo = (const float*)d_in[7];
    const float* bo = (const float*)d_in[8];
    float* out = (float*)d_out;

    __half *qp, *kp, *vp, *op, *xh, *wt;
    cudaGetSymbolAddress((void**)&qp, g_q);
    cudaGetSymbolAddress((void**)&kp, g_k);
    cudaGetSymbolAddress((void**)&vp, g_v);
    cudaGetSymbolAddress((void**)&op, g_o);
    cudaGetSymbolAddress((void**)&xh, g_xh);
    cudaGetSymbolAddress((void**)&wt, g_wt);
    __half* wto = wt + 3 * (size_t)Cdim * Cdim;

    cudaFuncSetAttribute(gemm_qkv_kernel,
                         cudaFuncAttributeMaxDynamicSharedMemorySize, GEMM_SMEM);
    cudaFuncSetAttribute(gemm_o_kernel,
                         cudaFuncAttributeMaxDynamicSharedMemorySize, GEMM_SMEM);
    cudaFuncSetAttribute(attn_mma_kernel,
                         cudaFuncAttributeMaxDynamicSharedMemorySize, ATTN_SMEM_BYTES);

    round_h_k<<<(Mrows * Cdim) / 1024, 256>>>(x, xh);
    dim3 tb(32, 8), tg(Cdim / 32, Cdim / 32, 4);
    transpose_h_k<<<tg, tb>>>(Wq, Wk, Wv, Wo, wt);

    dim3 gq(Cdim / GBN, Mrows / GBM, 3);   // (8, 32, 3)
    gemm_qkv_kernel<<<gq, GTH, GEMM_SMEM>>>(xh, wt, bq, bk, bv, qp, kp, vp);

    dim3 ga(Tseq / ABQ, Hh, Bsz);          // (16, 16, 2)
    attn_mma_kernel<<<ga, 256, ATTN_SMEM_BYTES>>>(qp, kp, vp, op);

    dim3 go(Cdim / GBN, Mrows / GBM);      // (8, 32)
    gemm_o_kernel<<<go, GTH, GEMM_SMEM>>>(op, wto, bo, out);
}

// round 10
// speedup vs baseline: 6.3265x; 1.0593x over previous
#include <cuda_runtime.h>
#include <cuda_fp16.h>
#include <math.h>
#include <stdint.h>

// Problem constants
#define Bsz  2
#define Tseq 2048
#define Cdim 2048
#define Hh   16
#define Dh   128
#define Mrows (Bsz*Tseq)   // 4096

// -------- scratch (device globals; no allocation allowed) --------
__device__ __half g_q[(size_t)Mrows * Cdim];
__device__ __half g_k[(size_t)Mrows * Cdim];
__device__ __half g_v[(size_t)Mrows * Cdim];
__device__ __half g_o[(size_t)Mrows * Cdim];
__device__ __half g_xh[(size_t)Mrows * Cdim];       // fp16 x
__device__ __half g_wt[4][(size_t)Cdim * Cdim];     // transposed fp16 weights

// ============================================================================
// Helpers
// ============================================================================
__device__ __forceinline__ uint32_t smem_u32(const void* p) {
    uint32_t a;
    asm("{ .reg .u64 t; cvta.to.shared.u64 t, %1; cvt.u32.u64 %0, t; }"
        : "=r"(a) : "l"(p));
    return a;
}

#define CP16(sa, ga) \
    asm volatile("cp.async.cg.shared.global [%0], [%1], 16;" \
                 :: "r"(sa), "l"(ga) : "memory")

#define MMA_F16(c, a0, a1, a2, a3, b0, b1) \
    asm volatile("mma.sync.aligned.m16n8k16.row.col.f32.f16.f16.f32 " \
        "{%0,%1,%2,%3},{%4,%5,%6,%7},{%8,%9},{%0,%1,%2,%3};" \
        : "+f"((c)[0]), "+f"((c)[1]), "+f"((c)[2]), "+f"((c)[3]) \
        : "r"(a0), "r"(a1), "r"(a2), "r"(a3), "r"(b0), "r"(b1))

#define LDSM4(r0, r1, r2, r3, addr) \
    asm volatile("ldmatrix.sync.aligned.m8n8.x4.shared.b16 {%0,%1,%2,%3}, [%4];" \
        : "=r"(r0), "=r"(r1), "=r"(r2), "=r"(r3) : "r"(addr))

#define LDSM4T(r0, r1, r2, r3, addr) \
    asm volatile("ldmatrix.sync.aligned.m8n8.x4.trans.shared.b16 {%0,%1,%2,%3}, [%4];" \
        : "=r"(r0), "=r"(r1), "=r"(r2), "=r"(r3) : "r"(addr))

#define SW(r) ((((r) >> 2) & 1) << 2)

__device__ __forceinline__ uint32_t pack_h2(float lo, float hi) {
    __half2 h = __floats2half2_rn(lo, hi);
    return *reinterpret_cast<uint32_t*>(&h);
}

// ============================================================================
// x -> fp16
// ============================================================================
__global__ __launch_bounds__(256) void round_h_k(
    const float* __restrict__ in, __half* __restrict__ out)
{
    size_t i = ((size_t)blockIdx.x * 256 + threadIdx.x) * 4;
    float4 v = *(const float4*)(in + i);
    *(__half2*)(out + i)     = __floats2half2_rn(v.x, v.y);
    *(__half2*)(out + i + 2) = __floats2half2_rn(v.z, v.w);
}

// ============================================================================
// Transpose 2048x2048 f32 -> fp16, all 4 weights in one launch (z selects)
// ============================================================================
__global__ __launch_bounds__(256) void transpose_h_k(
    const float* __restrict__ w0, const float* __restrict__ w1,
    const float* __restrict__ w2, const float* __restrict__ w3,
    __half* __restrict__ outbase)
{
    __shared__ float t[32][33];
    const int z = blockIdx.z;
    const float* in = (z == 0) ? w0 : (z == 1) ? w1 : (z == 2) ? w2 : w3;
    __half* out = outbase + (size_t)z * Cdim * Cdim;
    const int tx = threadIdx.x, ty = threadIdx.y;
    const int x = blockIdx.x * 32 + tx;
    const int y0 = blockIdx.y * 32;
#pragma unroll
    for (int i = 0; i < 32; i += 8)
        t[ty + i][tx] = in[(size_t)(y0 + ty + i) * Cdim + x];
    __syncthreads();
    const int xo = blockIdx.y * 32 + tx;
    const int yo0 = blockIdx.x * 32;
#pragma unroll
    for (int i = 0; i < 32; i += 8)
        out[(size_t)(yo0 + ty + i) * Cdim + xo] = __float2half_rn(t[tx][ty + i]);
}

// ============================================================================
// fp16 mma.sync GEMM with ldmatrix: C[M,2048] = A @ Bt^T + bias
// CTA 128x128, BK=64 halves, 3-stage cp.async, 8 warps (2x4), warp 64x32.
// 96KB smem + <=128 regs -> 2 CTAs per SM.
// ============================================================================
#define GBM 128
#define GBN 128
#define GBK 64
#define NST 3
#define GTH 256
#define A_U32 (GBM * GBK / 2)              // 4096
#define B_U32 (GBN * GBK / 2)              // 4096
#define STAGE_U32 (A_U32 + B_U32)          // 8192
#define STAGE_BYTES (STAGE_U32 * 4)        // 32768
#define GEMM_SMEM (NST * STAGE_BYTES)      // 98304

template<typename OutT>
__device__ __forceinline__ void gemm_body_h(
    const __half* __restrict__ A, const __half* __restrict__ Bt,
    const float* __restrict__ bias, OutT* __restrict__ Cm,
    uint32_t smbase)
{
    const int tid  = threadIdx.x;
    const int lane = tid & 31;
    const int wid  = tid >> 5;
    const int wm   = wid >> 2;       // 0..1
    const int wn   = wid & 3;        // 0..3
    const int m0   = blockIdx.y * GBM;
    const int n0   = blockIdx.x * GBN;
    const int g    = lane >> 2;
    const int t    = lane & 3;
    const int l15  = lane & 15;

    // ldmatrix byte offsets (within a k16-step block of 1024 u32)
    uint32_t offA[4], offB[2];
#pragma unroll
    for (int mi = 0; mi < 4; ++mi) {
        int r = wm * 64 + mi * 16 + l15;
        int c = lane >> 4;
        offA[mi] = 4u * (uint32_t)(r * 8 + ((c << 2) ^ SW(r)));
    }
#pragma unroll
    for (int nj = 0; nj < 2; ++nj) {
        int r = wn * 32 + nj * 16 + ((lane >> 4) << 3) + (lane & 7);
        int c = (lane >> 3) & 1;
        offB[nj] = 4u * (uint32_t)(r * 8 + ((c << 2) ^ SW(r)));
    }

    float acc[4][4][4];
#pragma unroll
    for (int mi = 0; mi < 4; ++mi)
#pragma unroll
        for (int ni = 0; ni < 4; ++ni)
#pragma unroll
            for (int x = 0; x < 4; ++x) acc[mi][ni][x] = 0.f;

    auto load_stage = [&](int s, int k0) {
        uint32_t ab = smbase + (uint32_t)s * STAGE_BYTES;
        uint32_t bb = ab + A_U32 * 4;
        const __half* Ap = A  + (size_t)m0 * Cdim + k0;
        const __half* Bp = Bt + (size_t)n0 * Cdim + k0;
#pragma unroll
        for (int i = 0; i < 4; ++i) {          // A: 128 rows x 8 chunks of 16B
            int lin = i * GTH + tid;
            int r   = lin >> 3;
            int cu  = (lin & 7) * 4;
            uint32_t off = 4u * (uint32_t)((cu >> 3) * 1024 + r * 8 + ((cu & 7) ^ SW(r)));
            CP16(ab + off, Ap + (size_t)r * Cdim + cu * 2);
        }
#pragma unroll
        for (int i = 0; i < 4; ++i) {          // B: 128 rows x 8 chunks
            int lin = i * GTH + tid;
            int r   = lin >> 3;
            int cu  = (lin & 7) * 4;
            uint32_t off = 4u * (uint32_t)((cu >> 3) * 1024 + r * 8 + ((cu & 7) ^ SW(r)));
            CP16(bb + off, Bp + (size_t)r * Cdim + cu * 2);
        }
    };

    load_stage(0, 0);
    asm volatile("cp.async.commit_group;" ::: "memory");
    load_stage(1, GBK);
    asm volatile("cp.async.commit_group;" ::: "memory");

    const int NIT = Cdim / GBK;            // 32
    for (int it = 0; it < NIT; ++it) {
        asm volatile("cp.async.wait_group 1;" ::: "memory");
        __syncthreads();

        const int nx = it + 2;
        if (nx < NIT) load_stage(nx % NST, nx * GBK);
        asm volatile("cp.async.commit_group;" ::: "memory");

        uint32_t abase = smbase + (uint32_t)(it % NST) * STAGE_BYTES;
        uint32_t bbase = abase + A_U32 * 4;

#pragma unroll
        for (int ks = 0; ks < 4; ++ks) {
            uint32_t a[4][4], b[2][4];
#pragma unroll
            for (int mi = 0; mi < 4; ++mi)
                LDSM4(a[mi][0], a[mi][1], a[mi][2], a[mi][3],
                      abase + ks * 4096 + offA[mi]);
#pragma unroll
            for (int nj = 0; nj < 2; ++nj)
                LDSM4(b[nj][0], b[nj][1], b[nj][2], b[nj][3],
                      bbase + ks * 4096 + offB[nj]);
#pragma unroll
            for (int mi = 0; mi < 4; ++mi)
#pragma unroll
                for (int nj = 0; nj < 2; ++nj) {
                    MMA_F16(acc[mi][2 * nj],     a[mi][0], a[mi][1], a[mi][2], a[mi][3],
                            b[nj][0], b[nj][1]);
                    MMA_F16(acc[mi][2 * nj + 1], a[mi][0], a[mi][1], a[mi][2], a[mi][3],
                            b[nj][2], b[nj][3]);
                }
        }
    }

#pragma unroll
    for (int mi = 0; mi < 4; ++mi) {
        int r0 = m0 + wm * 64 + mi * 16 + g;
#pragma unroll
        for (int ni = 0; ni < 4; ++ni) {
            int col = n0 + wn * 32 + ni * 8 + 2 * t;
            float2 bb = *(const float2*)(bias + col);
            float v0 = acc[mi][ni][0] + bb.x, v1 = acc[mi][ni][1] + bb.y;
            float v2 = acc[mi][ni][2] + bb.x, v3 = acc[mi][ni][3] + bb.y;
            if (sizeof(OutT) == 2) {
                __half* C = (__half*)Cm;
                *(__half2*)(C + (size_t)r0 * Cdim + col)       = __floats2half2_rn(v0, v1);
                *(__half2*)(C + (size_t)(r0 + 8) * Cdim + col) = __floats2half2_rn(v2, v3);
            } else {
                float* C = (float*)Cm;
                *(float2*)(C + (size_t)r0 * Cdim + col)       = make_float2(v0, v1);
                *(float2*)(C + (size_t)(r0 + 8) * Cdim + col) = make_float2(v2, v3);
            }
        }
    }
}

__global__ __launch_bounds__(GTH, 2) void gemm_qkv_kernel(
    const __half* __restrict__ A, const __half* __restrict__ WtBase,
    const float* __restrict__ bq, const float* __restrict__ bk,
    const float* __restrict__ bv,
    __half* __restrict__ Cq, __half* __restrict__ Ck, __half* __restrict__ Cv)
{
    extern __shared__ uint32_t smu[];
    const int z = blockIdx.z;
    const __half* Bt  = WtBase + (size_t)z * Cdim * Cdim;
    const float* bias = (z == 0) ? bq : (z == 1) ? bk : bv;
    __half*      Cm   = (z == 0) ? Cq : (z == 1) ? Ck : Cv;
    gemm_body_h<__half>(A, Bt, bias, Cm, smem_u32(smu));
}

__global__ __launch_bounds__(GTH, 2) void gemm_o_kernel(
    const __half* __restrict__ A, const __half* __restrict__ Bt,
    const float* __restrict__ bias, float* __restrict__ Cm)
{
    extern __shared__ uint32_t smu[];
    gemm_body_h<float>(A, Bt, bias, Cm, smem_u32(smu));
}

// ============================================================================
// fp16 flash attention (unchanged from R9): hoisted Q fragments, register P,
// ldmatrix.trans V. CTA: 128 queries, 8 warps; key tiles of 64; D=128.
//   Q [0,8192) | K 2x4096 @8192 | V 2x4096 @16384   (total 98304 B)
// ============================================================================
#define ABQ 128
#define ABK 64
#define KS_OFF   8192
#define KS_STRIDE 4096
#define VS_OFF   16384
#define VS_STRIDE 4096
#define ATTN_U32 (VS_OFF + 2 * VS_STRIDE)      // 24576
#define ATTN_SMEM_BYTES (ATTN_U32 * 4)         // 98304

__global__ __launch_bounds__(256, 1) void attn_mma_kernel(
    const __half* __restrict__ q, const __half* __restrict__ k,
    const __half* __restrict__ v, __half* __restrict__ o)
{
    extern __shared__ uint32_t smu[];
    const uint32_t smb = smem_u32(smu);
    const int tid  = threadIdx.x;
    const int lane = tid & 31;
    const int w    = tid >> 5;
    const int g    = lane >> 2;
    const int t    = lane & 3;
    const int l15  = lane & 15;

    const int qbase = (gridDim.x - 1 - blockIdx.x) * ABQ;   // long CTAs first
    const int h = blockIdx.y;
    const int b = blockIdx.z;
    const float scale = 0.08838834764831845f;           // 1/sqrt(128)
    const float slope = exp2f(-0.5f * (float)(h + 1));  // ALiBi slope, H=16
    const size_t headoff = (size_t)b * Tseq * Cdim + (size_t)h * Dh;

    // ---- Q tile: 128 rows x 64 u32 ----
    {
        const __half* qp = q + headoff + (size_t)qbase * Cdim;
#pragma unroll
        for (int l = 0; l < 8; ++l) {
            int lin = l * 256 + tid;
            int r   = lin >> 4;
            int cu  = (lin & 15) * 4;
            uint32_t off = (uint32_t)((cu >> 3) * 1024 + r * 8 + ((cu & 7) ^ SW(r)));
            CP16(smb + 4u * off, qp + (size_t)r * Cdim + cu * 2);
        }
    }

    const int ntiles = (qbase >> 6) + 2;

    auto loadKV = [&](int s, int kb) {
        const __half* kp = k + headoff + (size_t)kb * Cdim;
        const __half* vp = v + headoff + (size_t)kb * Cdim;
        uint32_t kbs = smb + 4u * (uint32_t)(KS_OFF + s * KS_STRIDE);
        uint32_t vbs = smb + 4u * (uint32_t)(VS_OFF + s * VS_STRIDE);
#pragma unroll
        for (int l = 0; l < 4; ++l) {
            int lin = l * 256 + tid;
            int r   = lin >> 4;
            int cu  = (lin & 15) * 4;
            uint32_t off = 4u * (uint32_t)((cu >> 3) * 512 + r * 8 + ((cu & 7) ^ SW(r)));
            CP16(kbs + off, kp + (size_t)r * Cdim + cu * 2);
            CP16(vbs + off, vp + (size_t)r * Cdim + cu * 2);
        }
    };
    loadKV(0, 0);
    asm volatile("cp.async.commit_group;" ::: "memory");

    uint32_t offQ;
    {
        int r = w * 16 + l15;
        int c = lane >> 4;
        offQ = 4u * (uint32_t)(r * 8 + ((c << 2) ^ SW(r)));
    }
    uint32_t offK[4];
#pragma unroll
    for (int nj = 0; nj < 4; ++nj) {
        int r = nj * 16 + ((lane >> 4) << 3) + (lane & 7);
        int c = (lane >> 3) & 1;
        offK[nj] = 4u * (uint32_t)(r * 8 + ((c << 2) ^ SW(r)));
    }
    uint32_t offV;
    {
        int p = lane >> 4;
        offV = 4u * (uint32_t)(l15 * 8 + ((p << 2) ^ SW(l15)));
    }

    asm volatile("cp.async.wait_group 0;" ::: "memory");
    __syncthreads();
    uint32_t qa[8][4];
#pragma unroll
    for (int ks = 0; ks < 8; ++ks)
        LDSM4(qa[ks][0], qa[ks][1], qa[ks][2], qa[ks][3], smb + ks * 4096 + offQ);

    float oacc[16][4];
#pragma unroll
    for (int i = 0; i < 16; ++i)
#pragma unroll
        for (int x = 0; x < 4; ++x) oacc[i][x] = 0.f;

    float mprev0 = -INFINITY, mprev1 = -INFINITY;
    float l0 = 0.f, l1 = 0.f;
    const int row0 = qbase + w * 16 + g;
    const int row1 = row0 + 8;

    for (int kt = 0; kt < ntiles; ++kt) {
        const int sk = kt & 1;
        const int kbase = kt * ABK;
        const uint32_t kbs = smb + 4u * (uint32_t)(KS_OFF + sk * KS_STRIDE);
        const uint32_t vbs = smb + 4u * (uint32_t)(VS_OFF + sk * VS_STRIDE);

        if (kt + 1 < ntiles) {
            loadKV(sk ^ 1, kbase + ABK);
            asm volatile("cp.async.commit_group;" ::: "memory");
        }

        // ---- S = Q K^T ----
        float sacc[8][4];
#pragma unroll
        for (int ni = 0; ni < 8; ++ni)
#pragma unroll
            for (int x = 0; x < 4; ++x) sacc[ni][x] = 0.f;

#pragma unroll
        for (int ks = 0; ks < 8; ++ks) {
#pragma unroll
            for (int nj = 0; nj < 4; ++nj) {
                uint32_t b0, b1, b2, b3;
                LDSM4(b0, b1, b2, b3, kbs + ks * 2048 + offK[nj]);
                MMA_F16(sacc[2 * nj],     qa[ks][0], qa[ks][1], qa[ks][2], qa[ks][3], b0, b1);
                MMA_F16(sacc[2 * nj + 1], qa[ks][0], qa[ks][1], qa[ks][2], qa[ks][3], b2, b3);
            }
        }

        // ---- scale + ALiBi + causal; online softmax ----
        float mt0 = -INFINITY, mt1 = -INFINITY;
#pragma unroll
        for (int ni = 0; ni < 8; ++ni) {
            int col = kbase + ni * 8 + 2 * t;
            float al0 = slope * (float)(col - (Tseq - 1));
            float al1 = slope * (float)(col + 1 - (Tseq - 1));
            float v0 = sacc[ni][0] * scale + al0;
            float v1 = sacc[ni][1] * scale + al1;
            float v2 = sacc[ni][2] * scale + al0;
            float v3 = sacc[ni][3] * scale + al1;
            if (col     > row0) v0 = -1e30f;
            if (col + 1 > row0) v1 = -1e30f;
            if (col     > row1) v2 = -1e30f;
            if (col + 1 > row1) v3 = -1e30f;
            sacc[ni][0] = v0; sacc[ni][1] = v1; sacc[ni][2] = v2; sacc[ni][3] = v3;
            mt0 = fmaxf(mt0, fmaxf(v0, v1));
            mt1 = fmaxf(mt1, fmaxf(v2, v3));
        }
        mt0 = fmaxf(mt0, __shfl_xor_sync(0xffffffffu, mt0, 1));
        mt0 = fmaxf(mt0, __shfl_xor_sync(0xffffffffu, mt0, 2));
        mt1 = fmaxf(mt1, __shfl_xor_sync(0xffffffffu, mt1, 1));
        mt1 = fmaxf(mt1, __shfl_xor_sync(0xffffffffu, mt1, 2));
        float mnew0 = fmaxf(mprev0, mt0);
        float mnew1 = fmaxf(mprev1, mt1);
        float corr0 = __expf(mprev0 - mnew0);
        float corr1 = __expf(mprev1 - mnew1);
        float sum0 = 0.f, sum1 = 0.f;
#pragma unroll
        for (int ni = 0; ni < 8; ++ni) {
            float p0 = __expf(sacc[ni][0] - mnew0);
            float p1 = __expf(sacc[ni][1] - mnew0);
            float p2 = __expf(sacc[ni][2] - mnew1);
            float p3 = __expf(sacc[ni][3] - mnew1);
            sum0 += p0 + p1; sum1 += p2 + p3;
            sacc[ni][0] = p0; sacc[ni][1] = p1; sacc[ni][2] = p2; sacc[ni][3] = p3;
        }
        sum0 += __shfl_xor_sync(0xffffffffu, sum0, 1);
        sum0 += __shfl_xor_sync(0xffffffffu, sum0, 2);
        sum1 += __shfl_xor_sync(0xffffffffu, sum1, 1);
        sum1 += __shfl_xor_sync(0xffffffffu, sum1, 2);
        l0 = l0 * corr0 + sum0;
        l1 = l1 * corr1 + sum1;
        mprev0 = mnew0; mprev1 = mnew1;
#pragma unroll
        for (int i = 0; i < 16; ++i) {
            oacc[i][0] *= corr0; oacc[i][1] *= corr0;
            oacc[i][2] *= corr1; oacc[i][3] *= corr1;
        }

        // ---- O += P V ----
#pragma unroll
        for (int ks = 0; ks < 4; ++ks) {
            uint32_t pa0 = pack_h2(sacc[2 * ks][0],     sacc[2 * ks][1]);
            uint32_t pa1 = pack_h2(sacc[2 * ks][2],     sacc[2 * ks][3]);
            uint32_t pa2 = pack_h2(sacc[2 * ks + 1][0], sacc[2 * ks + 1][1]);
            uint32_t pa3 = pack_h2(sacc[2 * ks + 1][2], sacc[2 * ks + 1][3]);
#pragma unroll
            for (int dj = 0; dj < 8; ++dj) {
                uint32_t b0, b1, b2, b3;
                LDSM4T(b0, b1, b2, b3, vbs + dj * 2048 + ks * 512 + offV);
                MMA_F16(oacc[2 * dj],     pa0, pa1, pa2, pa3, b0, b1);
                MMA_F16(oacc[2 * dj + 1], pa0, pa1, pa2, pa3, b2, b3);
            }
        }

        if (kt + 1 < ntiles) {
            asm volatile("cp.async.wait_group 0;" ::: "memory");
            __syncthreads();
        }
    }

    // ---- epilogue ----
    float inv0 = 1.f / l0, inv1 = 1.f / l1;
    __half* op0 = o + headoff + (size_t)row0 * Cdim;
    __half* op1 = o + headoff + (size_t)row1 * Cdim;
#pragma unroll
    for (int d = 0; d < 16; ++d) {
        int col = d * 8 + 2 * t;
        *(__half2*)(op0 + col) = __floats2half2_rn(oacc[d][0] * inv0, oacc[d][1] * inv0);
        *(__half2*)(op1 + col) = __floats2half2_rn(oacc[d][2] * inv1, oacc[d][3] * inv1);
    }
}

// ============================================================================
// Launch
// ============================================================================
extern "C" void kernel_launch(void* const* d_in, const int* in_sizes, int n_in,
                              void* d_out, int out_size)
{
    const float* x  = (const float*)d_in[0];
    const float* Wq = (const float*)d_in[1];
    const float* bq = (const float*)d_in[2];
    const float* Wk = (const float*)d_in[3];
    const float* bk = (const float*)d_in[4];
    const float* Wv = (const float*)d_in[5];
    const float* bv = (const float*)d_in[6];
    const float* Wo = (const float*)d_in[7];
    const float* bo = (const float*)d_in[8];
    float* out = (float*)d_out;

    __half *qp, *kp, *vp, *op, *xh, *wt;
    cudaGetSymbolAddress((void**)&qp, g_q);
    cudaGetSymbolAddress((void**)&kp, g_k);
    cudaGetSymbolAddress((void**)&vp, g_v);
    cudaGetSymbolAddress((void**)&op, g_o);
    cudaGetSymbolAddress((void**)&xh, g_xh);
    cudaGetSymbolAddress((void**)&wt, g_wt);
    __half* wto = wt + 3 * (size_t)Cdim * Cdim;

    cudaFuncSetAttribute(gemm_qkv_kernel,
                         cudaFuncAttributeMaxDynamicSharedMemorySize, GEMM_SMEM);
    cudaFuncSetAttribute(gemm_o_kernel,
                         cudaFuncAttributeMaxDynamicSharedMemorySize, GEMM_SMEM);
    cudaFuncSetAttribute(attn_mma_kernel,
                         cudaFuncAttributeMaxDynamicSharedMemorySize, ATTN_SMEM_BYTES);

    round_h_k<<<(Mrows * Cdim) / 1024, 256>>>(x, xh);
    dim3 tb(32, 8), tg(Cdim / 32, Cdim / 32, 4);
    transpose_h_k<<<tg, tb>>>(Wq, Wk, Wv, Wo, wt);

    dim3 gq(Cdim / GBN, Mrows / GBM, 3);   // (16, 32, 3)
    gemm_qkv_kernel<<<gq, GTH, GEMM_SMEM>>>(xh, wt, bq, bk, bv, qp, kp, vp);

    dim3 ga(Tseq / ABQ, Hh, Bsz);          // (16, 16, 2)
    attn_mma_kernel<<<ga, 256, ATTN_SMEM_BYTES>>>(qp, kp, vp, op);

    dim3 go(Cdim / GBN, Mrows / GBM);      // (16, 32)
    gemm_o_kernel<<<go, GTH, GEMM_SMEM>>>(op, wto, bo, out);
}